// round 4
// baseline (speedup 1.0000x reference)
#include <cuda_runtime.h>
#include <cuda_bf16.h>
#include <math.h>
#include <stdint.h>
#include <stddef.h>

typedef __nv_bfloat16 bf16;

#define BATCH 16
#define NTOK  3136
#define CH    768
#define NH    16
#define HD    48
#define KDIM  768
#define MROWS (BATCH*NTOK)   // 50176

// ----------------------------- device scratch ------------------------------
__device__ bf16  g_xhi[(size_t)MROWS * KDIM];
__device__ bf16  g_xlo[(size_t)MROWS * KDIM];
__device__ float g_qkv[(size_t)MROWS * 3 * CH];
__device__ bf16  g_ahi[(size_t)MROWS * CH];
__device__ bf16  g_alo[(size_t)MROWS * CH];
__device__ bf16  g_wqhi[(size_t)(3 * CH) * KDIM];
__device__ bf16  g_wqlo[(size_t)(3 * CH) * KDIM];
__device__ bf16  g_wphi[(size_t)CH * KDIM];
__device__ bf16  g_wplo[(size_t)CH * KDIM];

// ----------------------------- PTX helpers ---------------------------------
__device__ __forceinline__ uint32_t smem_u32(const void* p) {
    return (uint32_t)__cvta_generic_to_shared(p);
}

__device__ __forceinline__ void mma16816(float* c, const uint32_t* a, const uint32_t* b) {
    asm volatile(
        "mma.sync.aligned.m16n8k16.row.col.f32.bf16.bf16.f32 "
        "{%0,%1,%2,%3}, {%4,%5,%6,%7}, {%8,%9}, {%0,%1,%2,%3};"
        : "+f"(c[0]), "+f"(c[1]), "+f"(c[2]), "+f"(c[3])
        : "r"(a[0]), "r"(a[1]), "r"(a[2]), "r"(a[3]), "r"(b[0]), "r"(b[1]));
}

__device__ __forceinline__ void ldsm4(uint32_t* r, uint32_t addr) {
    asm volatile("ldmatrix.sync.aligned.m8n8.x4.shared.b16 {%0,%1,%2,%3}, [%4];"
        : "=r"(r[0]), "=r"(r[1]), "=r"(r[2]), "=r"(r[3]) : "r"(addr));
}

#define CP16(dst, src) \
    asm volatile("cp.async.cg.shared.global [%0], [%1], 16;" :: "r"(dst), "l"(src))
#define CP_COMMIT()  asm volatile("cp.async.commit_group;" ::: "memory")
#define CP_WAIT1()   asm volatile("cp.async.wait_group 1;" ::: "memory")

// ---------------------------------------------------------------------------
// fp32 -> bf16 hi/lo split
// ---------------------------------------------------------------------------
__global__ void split_kernel(const float4* __restrict__ in,
                             __nv_bfloat162* __restrict__ hi,
                             __nv_bfloat162* __restrict__ lo, int n4)
{
    int i = blockIdx.x * blockDim.x + threadIdx.x;
    if (i >= n4) return;
    float4 v = in[i];
    bf16 h0 = __float2bfloat16(v.x), h1 = __float2bfloat16(v.y);
    bf16 h2 = __float2bfloat16(v.z), h3 = __float2bfloat16(v.w);
    bf16 l0 = __float2bfloat16(v.x - __bfloat162float(h0));
    bf16 l1 = __float2bfloat16(v.y - __bfloat162float(h1));
    bf16 l2 = __float2bfloat16(v.z - __bfloat162float(h2));
    bf16 l3 = __float2bfloat16(v.w - __bfloat162float(h3));
    hi[2 * i + 0] = __halves2bfloat162(h0, h1);
    hi[2 * i + 1] = __halves2bfloat162(h2, h3);
    lo[2 * i + 0] = __halves2bfloat162(l0, l1);
    lo[2 * i + 1] = __halves2bfloat162(l2, l3);
}

// ---------------------------------------------------------------------------
// Transpose + split: W[K,N] row-major (fp32) -> Wt_hi/lo [N,K] (bf16)
// ---------------------------------------------------------------------------
__global__ void tsplit_kernel(const float* __restrict__ W,
                              bf16* __restrict__ Thi, bf16* __restrict__ Tlo,
                              int K, int N)
{
    __shared__ float tile[32][33];
    int n0 = blockIdx.x * 32, k0 = blockIdx.y * 32;
    int tx = threadIdx.x, ty = threadIdx.y;   // 32 x 8
#pragma unroll
    for (int j = 0; j < 32; j += 8)
        tile[ty + j][tx] = W[(size_t)(k0 + ty + j) * N + n0 + tx];
    __syncthreads();
#pragma unroll
    for (int j = 0; j < 32; j += 8) {
        float v = tile[tx][ty + j];
        bf16 h = __float2bfloat16(v);
        bf16 l = __float2bfloat16(v - __bfloat162float(h));
        size_t o = (size_t)(n0 + ty + j) * K + k0 + tx;
        Thi[o] = h;
        Tlo[o] = l;
    }
}

// ---------------------------------------------------------------------------
// bf16x3 mma.sync GEMM: C[M,N] = Ahi*Bhi^T + Alo*Bhi^T + Ahi*Blo^T (+bias)
// CTA tile 128x128, K-chunk 32, THREE-stage cp.async pipeline (one barrier
// per iteration), fragment double-buffering across the two k16 steps.
// 8 warps @ 64x32. SMEM rows padded to 80B: conflict-free ldmatrix/cp.async.
// ---------------------------------------------------------------------------
#define ROWB     80
#define TILE_B   (128 * ROWB)                // 10240
#define STAGE_B  (4 * TILE_B)                // 40960
#define NSTAGE   3
#define SMEM_GEMM (NSTAGE * STAGE_B)         // 122880
#define NITER    (KDIM / 32)                 // 24 k16-steps / 2

__global__ __launch_bounds__(256, 1) void gemm_mma(
    const bf16* __restrict__ Ahi, const bf16* __restrict__ Alo,
    const bf16* __restrict__ Bhi, const bf16* __restrict__ Blo,
    float* __restrict__ C, int N, const float* __restrict__ bias)
{
    extern __shared__ char sm[];
    const int tid  = threadIdx.x;
    const int wid  = tid >> 5;
    const int lane = tid & 31;

    const size_t m0 = (size_t)blockIdx.y * 128;
    const size_t n0 = (size_t)blockIdx.x * 128;

    // ---- loader: 4 tiles x 64 threads, 8 x 16B chunks per thread ----
    const int ltile = tid >> 6;
    const int lsub  = tid & 63;
    const int lrow0 = lsub >> 2;
    const int lseg  = lsub & 3;
    const bf16* lsrc;
    {
        const bf16* s0 = Ahi + m0 * KDIM;
        const bf16* s1 = Alo + m0 * KDIM;
        const bf16* s2 = Bhi + n0 * KDIM;
        const bf16* s3 = Blo + n0 * KDIM;
        lsrc = (ltile == 0) ? s0 : (ltile == 1) ? s1 : (ltile == 2) ? s2 : s3;
    }
    const uint32_t sbase = smem_u32(sm);
    const uint32_t ldst0 = sbase + ltile * TILE_B + lrow0 * ROWB + lseg * 16;
    const bf16* lsrc0 = lsrc + (size_t)lrow0 * KDIM + lseg * 8;

    auto load_stage = [&](int kc, int s) {
        uint32_t d = ldst0 + s * STAGE_B;
        const bf16* g = lsrc0 + kc;
#pragma unroll
        for (int i = 0; i < 8; i++)
            CP16(d + i * 16 * ROWB, g + (size_t)i * 16 * KDIM);
    };

    // ---- compute setup ----
    const int warp_m = wid & 1;
    const int warp_n = wid >> 1;
    const int g  = lane >> 3;
    const int r8 = lane & 7;
    const uint32_t a_off = (uint32_t)((warp_m * 64 + (g & 1) * 8 + r8) * ROWB + (g >> 1) * 16);
    const uint32_t b_off = (uint32_t)((warp_n * 32 + ((g >> 1) & 1) * 8 + r8) * ROWB + (g & 1) * 16);

    float acc[4][4][4];
#pragma unroll
    for (int i = 0; i < 4; i++)
#pragma unroll
        for (int j = 0; j < 4; j++)
#pragma unroll
            for (int q = 0; q < 4; q++) acc[i][j][q] = 0.f;

    uint32_t ah[2][4][4], al[2][4][4], bh[2][4][2], bl[2][4][2];

    auto load_frags = [&](uint32_t st, int kk, int buf) {
        const uint32_t kb = kk * 32;
#pragma unroll
        for (int mt = 0; mt < 4; mt++) {
            ldsm4(ah[buf][mt], st + 0 * TILE_B + a_off + mt * 16 * ROWB + kb);
            ldsm4(al[buf][mt], st + 1 * TILE_B + a_off + mt * 16 * ROWB + kb);
        }
#pragma unroll
        for (int j = 0; j < 2; j++) {
            uint32_t t4[4];
            ldsm4(t4, st + 2 * TILE_B + b_off + j * 16 * ROWB + kb);
            bh[buf][j * 2 + 0][0] = t4[0]; bh[buf][j * 2 + 0][1] = t4[1];
            bh[buf][j * 2 + 1][0] = t4[2]; bh[buf][j * 2 + 1][1] = t4[3];
            ldsm4(t4, st + 3 * TILE_B + b_off + j * 16 * ROWB + kb);
            bl[buf][j * 2 + 0][0] = t4[0]; bl[buf][j * 2 + 0][1] = t4[1];
            bl[buf][j * 2 + 1][0] = t4[2]; bl[buf][j * 2 + 1][1] = t4[3];
        }
    };

    // ---- prologue: fill stages 0 and 1 ----
    load_stage(0, 0);
    CP_COMMIT();
    load_stage(32, 1);
    CP_COMMIT();

    // ---- mainloop: one barrier per iteration ----
    for (int it = 0; it < NITER; it++) {
        CP_WAIT1();                // stage it%3 resident
        __syncthreads();           // all warps done reading stage (it+2)%3
        if (it + 2 < NITER)
            load_stage((it + 2) * 32, (it + 2) % NSTAGE);
        CP_COMMIT();               // commit every iter (may be empty group)

        const uint32_t st = sbase + (it % NSTAGE) * STAGE_B;
        load_frags(st, 0, 0);
#pragma unroll
        for (int kk = 0; kk < 2; kk++) {
            if (kk == 0) load_frags(st, 1, 1);   // prefetch next k16 frags
            const int fb = kk;
#pragma unroll
            for (int mt = 0; mt < 4; mt++)
#pragma unroll
                for (int nt = 0; nt < 4; nt++)
                    mma16816(acc[mt][nt], ah[fb][mt], bh[fb][nt]);
#pragma unroll
            for (int mt = 0; mt < 4; mt++)
#pragma unroll
                for (int nt = 0; nt < 4; nt++)
                    mma16816(acc[mt][nt], al[fb][mt], bh[fb][nt]);
#pragma unroll
            for (int mt = 0; mt < 4; mt++)
#pragma unroll
                for (int nt = 0; nt < 4; nt++)
                    mma16816(acc[mt][nt], ah[fb][mt], bl[fb][nt]);
        }
    }

    // ---- epilogue ----
    const int crow = warp_m * 64 + (lane >> 2);
    const int ccol = warp_n * 32 + (lane & 3) * 2;
#pragma unroll
    for (int mt = 0; mt < 4; mt++) {
#pragma unroll
        for (int nt = 0; nt < 4; nt++) {
            float b0 = 0.f, b1 = 0.f;
            if (bias) {
                b0 = __ldg(bias + n0 + ccol + nt * 8);
                b1 = __ldg(bias + n0 + ccol + nt * 8 + 1);
            }
            float2 v0 = {acc[mt][nt][0] + b0, acc[mt][nt][1] + b1};
            float2 v1 = {acc[mt][nt][2] + b0, acc[mt][nt][3] + b1};
            float* p0 = C + (m0 + crow + mt * 16) * (size_t)N + n0 + ccol + nt * 8;
            float* p1 = p0 + 8 * (size_t)N;
            *(float2*)p0 = v0;
            *(float2*)p1 = v1;
        }
    }
}

// ---------------------------------------------------------------------------
// Fused cross-covariance attention core (one CTA per (b,h)).
// ---------------------------------------------------------------------------
__global__ __launch_bounds__(256) void xca_kernel(const float* __restrict__ temperature)
{
    __shared__ float qs[32][48];
    __shared__ float ks[32][48];
    __shared__ float attn[48][52];
    __shared__ float invq[48];
    __shared__ float invk[48];

    const int bh = blockIdx.x;
    const int b = bh >> 4;
    const int h = bh & 15;
    const float* base = g_qkv + (size_t)b * NTOK * (3 * CH) + (size_t)h * HD;
    const int tid = threadIdx.x;
    const int r = tid >> 4;
    const int c = tid & 15;

    float acc[3][3];
#pragma unroll
    for (int i = 0; i < 3; i++)
#pragma unroll
        for (int j = 0; j < 3; j++) acc[i][j] = 0.f;
    float ssq[3] = {0.f, 0.f, 0.f};
    float ssk[3] = {0.f, 0.f, 0.f};

    for (int n0 = 0; n0 < NTOK; n0 += 32) {
        __syncthreads();
#pragma unroll
        for (int i = 0; i < 2; i++) {
            int idx = tid + i * 256;
            if (idx < 384) {
                int n = idx / 12;
                int m = (idx % 12) * 4;
                const float* p = base + (size_t)(n0 + n) * (3 * CH) + m;
                *(float4*)&qs[n][m] = *(const float4*)p;
                *(float4*)&ks[n][m] = *(const float4*)(p + CH);
            }
        }
        __syncthreads();
#pragma unroll 2
        for (int n = 0; n < 32; n++) {
            float q0 = qs[n][3 * r], q1 = qs[n][3 * r + 1], q2 = qs[n][3 * r + 2];
            float k0 = ks[n][3 * c], k1 = ks[n][3 * c + 1], k2 = ks[n][3 * c + 2];
            acc[0][0] = fmaf(q0, k0, acc[0][0]);
            acc[0][1] = fmaf(q0, k1, acc[0][1]);
            acc[0][2] = fmaf(q0, k2, acc[0][2]);
            acc[1][0] = fmaf(q1, k0, acc[1][0]);
            acc[1][1] = fmaf(q1, k1, acc[1][1]);
            acc[1][2] = fmaf(q1, k2, acc[1][2]);
            acc[2][0] = fmaf(q2, k0, acc[2][0]);
            acc[2][1] = fmaf(q2, k1, acc[2][1]);
            acc[2][2] = fmaf(q2, k2, acc[2][2]);
            if (c == 0) {
                ssq[0] = fmaf(q0, q0, ssq[0]);
                ssq[1] = fmaf(q1, q1, ssq[1]);
                ssq[2] = fmaf(q2, q2, ssq[2]);
            }
            if (r == 0) {
                ssk[0] = fmaf(k0, k0, ssk[0]);
                ssk[1] = fmaf(k1, k1, ssk[1]);
                ssk[2] = fmaf(k2, k2, ssk[2]);
            }
        }
    }

    if (c == 0) {
        invq[3 * r + 0] = ssq[0];
        invq[3 * r + 1] = ssq[1];
        invq[3 * r + 2] = ssq[2];
    }
    if (r == 0) {
        invk[3 * c + 0] = ssk[0];
        invk[3 * c + 1] = ssk[1];
        invk[3 * c + 2] = ssk[2];
    }
    __syncthreads();
    if (tid < 48) {
        invq[tid] = 1.f / fmaxf(sqrtf(invq[tid]), 1e-12f);
    } else if (tid < 96) {
        invk[tid - 48] = 1.f / fmaxf(sqrtf(invk[tid - 48]), 1e-12f);
    }
    __syncthreads();

    const float temp = temperature[h];
#pragma unroll
    for (int i = 0; i < 3; i++)
#pragma unroll
        for (int j = 0; j < 3; j++)
            attn[3 * r + i][3 * c + j] =
                acc[i][j] * invq[3 * r + i] * invk[3 * c + j] * temp;
    __syncthreads();

    const int lane = tid & 31;
    const int w = tid >> 5;
    for (int d = w; d < 48; d += 8) {
        float x1 = attn[d][lane];
        float x2 = (lane < 16) ? attn[d][32 + lane] : -1e30f;
        float m = fmaxf(x1, x2);
#pragma unroll
        for (int o = 16; o > 0; o >>= 1)
            m = fmaxf(m, __shfl_xor_sync(0xffffffffu, m, o));
        float p1 = expf(x1 - m);
        float p2 = (lane < 16) ? expf(x2 - m) : 0.f;
        float s = p1 + p2;
#pragma unroll
        for (int o = 16; o > 0; o >>= 1)
            s += __shfl_xor_sync(0xffffffffu, s, o);
        float inv = 1.f / s;
        attn[d][lane] = p1 * inv;
        if (lane < 16) attn[d][32 + lane] = p2 * inv;
    }
    __syncthreads();

    bf16* outhi = g_ahi + (size_t)b * NTOK * CH + (size_t)h * HD;
    bf16* outlo = g_alo + (size_t)b * NTOK * CH + (size_t)h * HD;
    const int d = tid % 48;
    const int vt = tid / 48;
    float areg[48];
    if (tid < 192) {
#pragma unroll
        for (int e = 0; e < 48; e++) areg[e] = attn[d][e];
    }

    for (int n0 = 0; n0 < NTOK; n0 += 16) {
        __syncthreads();
        if (tid < 192) {
            int n = tid / 12;
            int m = (tid % 12) * 4;
            *(float4*)&qs[n][m] =
                *(const float4*)(base + (size_t)(n0 + n) * (3 * CH) + 2 * CH + m);
        }
        __syncthreads();
        if (tid < 192) {
            int nb = vt * 4;
            float o0 = 0.f, o1 = 0.f, o2 = 0.f, o3 = 0.f;
#pragma unroll
            for (int e = 0; e < 48; e++) {
                float a = areg[e];
                o0 = fmaf(a, qs[nb + 0][e], o0);
                o1 = fmaf(a, qs[nb + 1][e], o1);
                o2 = fmaf(a, qs[nb + 2][e], o2);
                o3 = fmaf(a, qs[nb + 3][e], o3);
            }
            float ov[4] = {o0, o1, o2, o3};
#pragma unroll
            for (int j = 0; j < 4; j++) {
                bf16 hh = __float2bfloat16(ov[j]);
                bf16 ll = __float2bfloat16(ov[j] - __bfloat162float(hh));
                size_t off = (size_t)(n0 + nb + j) * CH + d;
                outhi[off] = hh;
                outlo[off] = ll;
            }
        }
    }
}

// ---------------------------------------------------------------------------
// Launch sequence
// ---------------------------------------------------------------------------
extern "C" void kernel_launch(void* const* d_in, const int* in_sizes, int n_in,
                              void* d_out, int out_size)
{
    const float* x           = (const float*)d_in[0];
    const float* qkv_w       = (const float*)d_in[1];
    const float* temperature = (const float*)d_in[2];
    const float* proj_w      = (const float*)d_in[3];
    const float* proj_b      = (const float*)d_in[4];
    float* out = (float*)d_out;

    bf16 *xhi, *xlo, *ahi, *alo, *wqhi, *wqlo, *wphi, *wplo;
    float* qkv_d;
    cudaGetSymbolAddress((void**)&xhi, g_xhi);
    cudaGetSymbolAddress((void**)&xlo, g_xlo);
    cudaGetSymbolAddress((void**)&ahi, g_ahi);
    cudaGetSymbolAddress((void**)&alo, g_alo);
    cudaGetSymbolAddress((void**)&wqhi, g_wqhi);
    cudaGetSymbolAddress((void**)&wqlo, g_wqlo);
    cudaGetSymbolAddress((void**)&wphi, g_wphi);
    cudaGetSymbolAddress((void**)&wplo, g_wplo);
    cudaGetSymbolAddress((void**)&qkv_d, g_qkv);

    cudaFuncSetAttribute(gemm_mma, cudaFuncAttributeMaxDynamicSharedMemorySize, SMEM_GEMM);

    int n4 = MROWS * KDIM / 4;
    split_kernel<<<(n4 + 255) / 256, 256>>>(
        (const float4*)x, (__nv_bfloat162*)xhi, (__nv_bfloat162*)xlo, n4);

    tsplit_kernel<<<dim3((3 * CH) / 32, KDIM / 32), dim3(32, 8)>>>(
        qkv_w, wqhi, wqlo, KDIM, 3 * CH);
    tsplit_kernel<<<dim3(CH / 32, KDIM / 32), dim3(32, 8)>>>(
        proj_w, wphi, wplo, KDIM, CH);

    gemm_mma<<<dim3((3 * CH) / 128, MROWS / 128), 256, SMEM_GEMM>>>(
        xhi, xlo, wqhi, wqlo, qkv_d, 3 * CH, nullptr);

    xca_kernel<<<BATCH * NH, 256>>>(temperature);

    gemm_mma<<<dim3(CH / 128, MROWS / 128), 256, SMEM_GEMM>>>(
        ahi, alo, wphi, wplo, out, CH, proj_b);
}

// round 5
// speedup vs baseline: 1.4780x; 1.4780x over previous
#include <cuda_runtime.h>
#include <cuda_fp16.h>
#include <math.h>
#include <stdint.h>
#include <stddef.h>

#define BATCH 16
#define NTOK  3136
#define CH    768
#define NH    16
#define HD    48
#define KDIM  768
#define MROWS (BATCH*NTOK)   // 50176

// ----------------------------- device scratch ------------------------------
__device__ __half g_xh [(size_t)MROWS * KDIM];            // x in fp16
__device__ float  g_qkv[(size_t)MROWS * 3 * CH];
__device__ __half g_ah [(size_t)MROWS * CH];              // attention out fp16
__device__ __half g_wqhi[(size_t)(3 * CH) * KDIM];        // qkv_w^T hi/lo
__device__ __half g_wqlo[(size_t)(3 * CH) * KDIM];
__device__ __half g_wphi[(size_t)CH * KDIM];              // proj_w^T hi/lo
__device__ __half g_wplo[(size_t)CH * KDIM];

// ----------------------------- PTX helpers ---------------------------------
__device__ __forceinline__ uint32_t smem_u32(const void* p) {
    return (uint32_t)__cvta_generic_to_shared(p);
}

__device__ __forceinline__ void mma16816(float* c, const uint32_t* a, const uint32_t* b) {
    asm volatile(
        "mma.sync.aligned.m16n8k16.row.col.f32.f16.f16.f32 "
        "{%0,%1,%2,%3}, {%4,%5,%6,%7}, {%8,%9}, {%0,%1,%2,%3};"
        : "+f"(c[0]), "+f"(c[1]), "+f"(c[2]), "+f"(c[3])
        : "r"(a[0]), "r"(a[1]), "r"(a[2]), "r"(a[3]), "r"(b[0]), "r"(b[1]));
}

__device__ __forceinline__ void ldsm4(uint32_t* r, uint32_t addr) {
    asm volatile("ldmatrix.sync.aligned.m8n8.x4.shared.b16 {%0,%1,%2,%3}, [%4];"
        : "=r"(r[0]), "=r"(r[1]), "=r"(r[2]), "=r"(r[3]) : "r"(addr));
}

#define CP16(dst, src) \
    asm volatile("cp.async.cg.shared.global [%0], [%1], 16;" :: "r"(dst), "l"(src))
#define CP_COMMIT()  asm volatile("cp.async.commit_group;" ::: "memory")
#define CP_WAIT1()   asm volatile("cp.async.wait_group 1;" ::: "memory")
#define CP_WAIT0()   asm volatile("cp.async.wait_group 0;" ::: "memory")

// ---------------------------------------------------------------------------
// fp32 -> fp16 convert (for x; no lo term needed)
// ---------------------------------------------------------------------------
__global__ void conv_kernel(const float4* __restrict__ in,
                            __half2* __restrict__ out, int n4)
{
    int i = blockIdx.x * blockDim.x + threadIdx.x;
    if (i >= n4) return;
    float4 v = in[i];
    out[2 * i + 0] = __floats2half2_rn(v.x, v.y);
    out[2 * i + 1] = __floats2half2_rn(v.z, v.w);
}

// ---------------------------------------------------------------------------
// Transpose + split: W[K,N] row-major fp32 -> Wt_hi/lo [N,K] fp16
// ---------------------------------------------------------------------------
__global__ void tsplit_kernel(const float* __restrict__ W,
                              __half* __restrict__ Thi, __half* __restrict__ Tlo,
                              int K, int N)
{
    __shared__ float tile[32][33];
    int n0 = blockIdx.x * 32, k0 = blockIdx.y * 32;
    int tx = threadIdx.x, ty = threadIdx.y;   // 32 x 8
#pragma unroll
    for (int j = 0; j < 32; j += 8)
        tile[ty + j][tx] = W[(size_t)(k0 + ty + j) * N + n0 + tx];
    __syncthreads();
#pragma unroll
    for (int j = 0; j < 32; j += 8) {
        float v = tile[tx][ty + j];
        __half h = __float2half_rn(v);
        __half l = __float2half_rn(v - __half2float(h));
        size_t o = (size_t)(n0 + ty + j) * K + k0 + tx;
        Thi[o] = h;
        Tlo[o] = l;
    }
}

// ---------------------------------------------------------------------------
// fp16 2-pass mma GEMM: C[M,N] = A*Bhi^T + A*Blo^T (+bias)
// A: [M,768] fp16 row-major.  Bhi/Blo: [N,768] fp16 (pre-transposed).
// CTA tile 128x128, K-chunk 32, 2-stage cp.async double buffer, 8 warps @64x32.
// SMEM rows padded to 80B: conflict-free ldmatrix/cp.async.
// ---------------------------------------------------------------------------
#define ROWB     80
#define TILE_B   (128 * ROWB)                // 10240
#define STAGE_B  (3 * TILE_B)                // A, Bhi, Blo = 30720
#define SMEM_GEMM (2 * STAGE_B)              // 61440
#define NITER    (KDIM / 32)                 // 24

__global__ __launch_bounds__(256) void gemm_mma(
    const __half* __restrict__ A,
    const __half* __restrict__ Bhi, const __half* __restrict__ Blo,
    float* __restrict__ C, int N, const float* __restrict__ bias)
{
    extern __shared__ char sm[];
    const int tid  = threadIdx.x;
    const int wid  = tid >> 5;
    const int lane = tid & 31;

    const size_t m0 = (size_t)blockIdx.y * 128;
    const size_t n0 = (size_t)blockIdx.x * 128;

    // ---- loader: 3 tiles x 64 threads (threads 192..255 idle on loads) ----
    const int ltile = tid >> 6;          // 0:A 1:Bhi 2:Blo 3:none
    const int lsub  = tid & 63;
    const int lrow0 = lsub >> 2;
    const int lseg  = lsub & 3;
    const __half* lsrc;
    {
        const __half* s0 = A   + m0 * KDIM;
        const __half* s1 = Bhi + n0 * KDIM;
        const __half* s2 = Blo + n0 * KDIM;
        lsrc = (ltile == 0) ? s0 : (ltile == 1) ? s1 : s2;
    }
    const uint32_t sbase = smem_u32(sm);
    const uint32_t ldst0 = sbase + ltile * TILE_B + lrow0 * ROWB + lseg * 16;
    const __half* lsrc0 = lsrc + (size_t)lrow0 * KDIM + lseg * 8;

    auto load_stage = [&](int kc, int s) {
        if (ltile < 3) {
            uint32_t d = ldst0 + s * STAGE_B;
            const __half* g = lsrc0 + kc;
#pragma unroll
            for (int i = 0; i < 8; i++)
                CP16(d + i * 16 * ROWB, g + (size_t)i * 16 * KDIM);
        }
    };

    // ---- compute setup: 8 warps, warp tile 64x32 ----
    const int warp_m = wid & 1;
    const int warp_n = wid >> 1;
    const int g  = lane >> 3;
    const int r8 = lane & 7;
    const uint32_t a_off = (uint32_t)((warp_m * 64 + (g & 1) * 8 + r8) * ROWB + (g >> 1) * 16);
    const uint32_t b_off = (uint32_t)((warp_n * 32 + ((g >> 1) & 1) * 8 + r8) * ROWB + (g & 1) * 16);

    float acc[4][4][4];
#pragma unroll
    for (int i = 0; i < 4; i++)
#pragma unroll
        for (int j = 0; j < 4; j++)
#pragma unroll
            for (int q = 0; q < 4; q++) acc[i][j][q] = 0.f;

    load_stage(0, 0);
    CP_COMMIT();

    for (int it = 0; it < NITER; it++) {
        const int s = it & 1;
        if (it + 1 < NITER) {
            load_stage((it + 1) * 32, s ^ 1);
            CP_COMMIT();
            CP_WAIT1();
        } else {
            CP_WAIT0();
        }
        __syncthreads();

        const uint32_t st = sbase + s * STAGE_B;
#pragma unroll
        for (int kk = 0; kk < 2; kk++) {
            const uint32_t kb = kk * 32;
            uint32_t af[4][4], bh[4][2], bl[4][2];
#pragma unroll
            for (int mt = 0; mt < 4; mt++)
                ldsm4(af[mt], st + 0 * TILE_B + a_off + mt * 16 * ROWB + kb);
#pragma unroll
            for (int j = 0; j < 2; j++) {
                uint32_t t4[4];
                ldsm4(t4, st + 1 * TILE_B + b_off + j * 16 * ROWB + kb);
                bh[j * 2 + 0][0] = t4[0]; bh[j * 2 + 0][1] = t4[1];
                bh[j * 2 + 1][0] = t4[2]; bh[j * 2 + 1][1] = t4[3];
                ldsm4(t4, st + 2 * TILE_B + b_off + j * 16 * ROWB + kb);
                bl[j * 2 + 0][0] = t4[0]; bl[j * 2 + 0][1] = t4[1];
                bl[j * 2 + 1][0] = t4[2]; bl[j * 2 + 1][1] = t4[3];
            }
            // pass 1: A * Bhi
#pragma unroll
            for (int mt = 0; mt < 4; mt++)
#pragma unroll
                for (int nt = 0; nt < 4; nt++)
                    mma16816(acc[mt][nt], af[mt], bh[nt]);
            // pass 2: A * Blo
#pragma unroll
            for (int mt = 0; mt < 4; mt++)
#pragma unroll
                for (int nt = 0; nt < 4; nt++)
                    mma16816(acc[mt][nt], af[mt], bl[nt]);
        }
        __syncthreads();
    }

    // ---- epilogue ----
    const int crow = warp_m * 64 + (lane >> 2);
    const int ccol = warp_n * 32 + (lane & 3) * 2;
#pragma unroll
    for (int mt = 0; mt < 4; mt++) {
#pragma unroll
        for (int nt = 0; nt < 4; nt++) {
            float b0 = 0.f, b1 = 0.f;
            if (bias) {
                b0 = __ldg(bias + n0 + ccol + nt * 8);
                b1 = __ldg(bias + n0 + ccol + nt * 8 + 1);
            }
            float2 v0 = {acc[mt][nt][0] + b0, acc[mt][nt][1] + b1};
            float2 v1 = {acc[mt][nt][2] + b0, acc[mt][nt][3] + b1};
            float* p0 = C + (m0 + crow + mt * 16) * (size_t)N + n0 + ccol + nt * 8;
            float* p1 = p0 + 8 * (size_t)N;
            *(float2*)p0 = v0;
            *(float2*)p1 = v1;
        }
    }
}

// ---------------------------------------------------------------------------
// Fused cross-covariance attention core (one CTA per (b,h)).
// Phase 3 emits fp16 directly for GEMM2's A operand.
// ---------------------------------------------------------------------------
__global__ __launch_bounds__(256) void xca_kernel(const float* __restrict__ temperature)
{
    __shared__ float qs[32][48];
    __shared__ float ks[32][48];
    __shared__ float attn[48][52];
    __shared__ float invq[48];
    __shared__ float invk[48];

    const int bh = blockIdx.x;
    const int b = bh >> 4;
    const int h = bh & 15;
    const float* base = g_qkv + (size_t)b * NTOK * (3 * CH) + (size_t)h * HD;
    const int tid = threadIdx.x;
    const int r = tid >> 4;
    const int c = tid & 15;

    float acc[3][3];
#pragma unroll
    for (int i = 0; i < 3; i++)
#pragma unroll
        for (int j = 0; j < 3; j++) acc[i][j] = 0.f;
    float ssq[3] = {0.f, 0.f, 0.f};
    float ssk[3] = {0.f, 0.f, 0.f};

    for (int n0 = 0; n0 < NTOK; n0 += 32) {
        __syncthreads();
#pragma unroll
        for (int i = 0; i < 2; i++) {
            int idx = tid + i * 256;
            if (idx < 384) {
                int n = idx / 12;
                int m = (idx % 12) * 4;
                const float* p = base + (size_t)(n0 + n) * (3 * CH) + m;
                *(float4*)&qs[n][m] = *(const float4*)p;
                *(float4*)&ks[n][m] = *(const float4*)(p + CH);
            }
        }
        __syncthreads();
#pragma unroll 2
        for (int n = 0; n < 32; n++) {
            float q0 = qs[n][3 * r], q1 = qs[n][3 * r + 1], q2 = qs[n][3 * r + 2];
            float k0 = ks[n][3 * c], k1 = ks[n][3 * c + 1], k2 = ks[n][3 * c + 2];
            acc[0][0] = fmaf(q0, k0, acc[0][0]);
            acc[0][1] = fmaf(q0, k1, acc[0][1]);
            acc[0][2] = fmaf(q0, k2, acc[0][2]);
            acc[1][0] = fmaf(q1, k0, acc[1][0]);
            acc[1][1] = fmaf(q1, k1, acc[1][1]);
            acc[1][2] = fmaf(q1, k2, acc[1][2]);
            acc[2][0] = fmaf(q2, k0, acc[2][0]);
            acc[2][1] = fmaf(q2, k1, acc[2][1]);
            acc[2][2] = fmaf(q2, k2, acc[2][2]);
            if (c == 0) {
                ssq[0] = fmaf(q0, q0, ssq[0]);
                ssq[1] = fmaf(q1, q1, ssq[1]);
                ssq[2] = fmaf(q2, q2, ssq[2]);
            }
            if (r == 0) {
                ssk[0] = fmaf(k0, k0, ssk[0]);
                ssk[1] = fmaf(k1, k1, ssk[1]);
                ssk[2] = fmaf(k2, k2, ssk[2]);
            }
        }
    }

    if (c == 0) {
        invq[3 * r + 0] = ssq[0];
        invq[3 * r + 1] = ssq[1];
        invq[3 * r + 2] = ssq[2];
    }
    if (r == 0) {
        invk[3 * c + 0] = ssk[0];
        invk[3 * c + 1] = ssk[1];
        invk[3 * c + 2] = ssk[2];
    }
    __syncthreads();
    if (tid < 48) {
        invq[tid] = 1.f / fmaxf(sqrtf(invq[tid]), 1e-12f);
    } else if (tid < 96) {
        invk[tid - 48] = 1.f / fmaxf(sqrtf(invk[tid - 48]), 1e-12f);
    }
    __syncthreads();

    const float temp = temperature[h];
#pragma unroll
    for (int i = 0; i < 3; i++)
#pragma unroll
        for (int j = 0; j < 3; j++)
            attn[3 * r + i][3 * c + j] =
                acc[i][j] * invq[3 * r + i] * invk[3 * c + j] * temp;
    __syncthreads();

    const int lane = tid & 31;
    const int w = tid >> 5;
    for (int d = w; d < 48; d += 8) {
        float x1 = attn[d][lane];
        float x2 = (lane < 16) ? attn[d][32 + lane] : -1e30f;
        float m = fmaxf(x1, x2);
#pragma unroll
        for (int o = 16; o > 0; o >>= 1)
            m = fmaxf(m, __shfl_xor_sync(0xffffffffu, m, o));
        float p1 = expf(x1 - m);
        float p2 = (lane < 16) ? expf(x2 - m) : 0.f;
        float s = p1 + p2;
#pragma unroll
        for (int o = 16; o > 0; o >>= 1)
            s += __shfl_xor_sync(0xffffffffu, s, o);
        float inv = 1.f / s;
        attn[d][lane] = p1 * inv;
        if (lane < 16) attn[d][32 + lane] = p2 * inv;
    }
    __syncthreads();

    __half* outp = g_ah + (size_t)b * NTOK * CH + (size_t)h * HD;
    const int d = tid % 48;
    const int vt = tid / 48;
    float areg[48];
    if (tid < 192) {
#pragma unroll
        for (int e = 0; e < 48; e++) areg[e] = attn[d][e];
    }

    for (int n0 = 0; n0 < NTOK; n0 += 16) {
        __syncthreads();
        if (tid < 192) {
            int n = tid / 12;
            int m = (tid % 12) * 4;
            *(float4*)&qs[n][m] =
                *(const float4*)(base + (size_t)(n0 + n) * (3 * CH) + 2 * CH + m);
        }
        __syncthreads();
        if (tid < 192) {
            int nb = vt * 4;
            float o0 = 0.f, o1 = 0.f, o2 = 0.f, o3 = 0.f;
#pragma unroll
            for (int e = 0; e < 48; e++) {
                float a = areg[e];
                o0 = fmaf(a, qs[nb + 0][e], o0);
                o1 = fmaf(a, qs[nb + 1][e], o1);
                o2 = fmaf(a, qs[nb + 2][e], o2);
                o3 = fmaf(a, qs[nb + 3][e], o3);
            }
            float ov[4] = {o0, o1, o2, o3};
#pragma unroll
            for (int j = 0; j < 4; j++)
                outp[(size_t)(n0 + nb + j) * CH + d] = __float2half_rn(ov[j]);
        }
    }
}

// ---------------------------------------------------------------------------
// Launch sequence
// ---------------------------------------------------------------------------
extern "C" void kernel_launch(void* const* d_in, const int* in_sizes, int n_in,
                              void* d_out, int out_size)
{
    const float* x           = (const float*)d_in[0];
    const float* qkv_w       = (const float*)d_in[1];
    const float* temperature = (const float*)d_in[2];
    const float* proj_w      = (const float*)d_in[3];
    const float* proj_b      = (const float*)d_in[4];
    float* out = (float*)d_out;

    __half *xh, *ah, *wqhi, *wqlo, *wphi, *wplo;
    float* qkv_d;
    cudaGetSymbolAddress((void**)&xh, g_xh);
    cudaGetSymbolAddress((void**)&ah, g_ah);
    cudaGetSymbolAddress((void**)&wqhi, g_wqhi);
    cudaGetSymbolAddress((void**)&wqlo, g_wqlo);
    cudaGetSymbolAddress((void**)&wphi, g_wphi);
    cudaGetSymbolAddress((void**)&wplo, g_wplo);
    cudaGetSymbolAddress((void**)&qkv_d, g_qkv);

    cudaFuncSetAttribute(gemm_mma, cudaFuncAttributeMaxDynamicSharedMemorySize, SMEM_GEMM);

    int n4 = MROWS * KDIM / 4;
    conv_kernel<<<(n4 + 255) / 256, 256>>>((const float4*)x, (__half2*)xh, n4);

    tsplit_kernel<<<dim3((3 * CH) / 32, KDIM / 32), dim3(32, 8)>>>(
        qkv_w, wqhi, wqlo, KDIM, 3 * CH);
    tsplit_kernel<<<dim3(CH / 32, KDIM / 32), dim3(32, 8)>>>(
        proj_w, wphi, wplo, KDIM, CH);

    gemm_mma<<<dim3((3 * CH) / 128, MROWS / 128), 256, SMEM_GEMM>>>(
        xh, wqhi, wqlo, qkv_d, 3 * CH, nullptr);

    xca_kernel<<<BATCH * NH, 256>>>(temperature);

    gemm_mma<<<dim3(CH / 128, MROWS / 128), 256, SMEM_GEMM>>>(
        ah, wphi, wplo, out, CH, proj_b);
}

// round 6
// speedup vs baseline: 1.7247x; 1.1669x over previous
#include <cuda_runtime.h>
#include <cuda_fp16.h>
#include <math.h>
#include <stdint.h>
#include <stddef.h>

#define BATCH 16
#define NTOK  3136
#define CH    768
#define NH    16
#define HD    48
#define KDIM  768
#define MROWS (BATCH*NTOK)   // 50176
#define BH    (BATCH*NH)     // 256
#define SPLIT 7
#define TOKSP (NTOK/SPLIT)   // 448

// ----------------------------- device scratch ------------------------------
__device__ __half g_xh [(size_t)MROWS * KDIM];
__device__ float  g_qkv[(size_t)MROWS * 3 * CH];
__device__ __half g_ah [(size_t)MROWS * CH];
__device__ __half g_wqhi[(size_t)(3 * CH) * KDIM];
__device__ __half g_wqlo[(size_t)(3 * CH) * KDIM];
__device__ __half g_wphi[(size_t)CH * KDIM];
__device__ __half g_wplo[(size_t)CH * KDIM];
__device__ float  g_gram[(size_t)BH * SPLIT * HD * HD];
__device__ float  g_ssq [(size_t)BH * SPLIT * HD];
__device__ float  g_ssk [(size_t)BH * SPLIT * HD];
__device__ float  g_attn[(size_t)BH * HD * HD];

// ----------------------------- PTX helpers ---------------------------------
__device__ __forceinline__ uint32_t smem_u32(const void* p) {
    return (uint32_t)__cvta_generic_to_shared(p);
}

__device__ __forceinline__ void mma16816(float* c, const uint32_t* a, const uint32_t* b) {
    asm volatile(
        "mma.sync.aligned.m16n8k16.row.col.f32.f16.f16.f32 "
        "{%0,%1,%2,%3}, {%4,%5,%6,%7}, {%8,%9}, {%0,%1,%2,%3};"
        : "+f"(c[0]), "+f"(c[1]), "+f"(c[2]), "+f"(c[3])
        : "r"(a[0]), "r"(a[1]), "r"(a[2]), "r"(a[3]), "r"(b[0]), "r"(b[1]));
}

__device__ __forceinline__ void ldsm4(uint32_t* r, uint32_t addr) {
    asm volatile("ldmatrix.sync.aligned.m8n8.x4.shared.b16 {%0,%1,%2,%3}, [%4];"
        : "=r"(r[0]), "=r"(r[1]), "=r"(r[2]), "=r"(r[3]) : "r"(addr));
}

#define CP16(dst, src) \
    asm volatile("cp.async.cg.shared.global [%0], [%1], 16;" :: "r"(dst), "l"(src))
#define CP_COMMIT()  asm volatile("cp.async.commit_group;" ::: "memory")
#define CP_WAIT1()   asm volatile("cp.async.wait_group 1;" ::: "memory")

// ---------------------------------------------------------------------------
// fp32 -> fp16 convert
// ---------------------------------------------------------------------------
__global__ void conv_kernel(const float4* __restrict__ in,
                            __half2* __restrict__ out, int n4)
{
    int i = blockIdx.x * blockDim.x + threadIdx.x;
    if (i >= n4) return;
    float4 v = in[i];
    out[2 * i + 0] = __floats2half2_rn(v.x, v.y);
    out[2 * i + 1] = __floats2half2_rn(v.z, v.w);
}

// ---------------------------------------------------------------------------
// Transpose + split: W[K,N] fp32 -> Wt_hi/lo [N,K] fp16
// ---------------------------------------------------------------------------
__global__ void tsplit_kernel(const float* __restrict__ W,
                              __half* __restrict__ Thi, __half* __restrict__ Tlo,
                              int K, int N)
{
    __shared__ float tile[32][33];
    int n0 = blockIdx.x * 32, k0 = blockIdx.y * 32;
    int tx = threadIdx.x, ty = threadIdx.y;   // 32 x 8
#pragma unroll
    for (int j = 0; j < 32; j += 8)
        tile[ty + j][tx] = W[(size_t)(k0 + ty + j) * N + n0 + tx];
    __syncthreads();
#pragma unroll
    for (int j = 0; j < 32; j += 8) {
        float v = tile[tx][ty + j];
        __half h = __float2half_rn(v);
        __half l = __float2half_rn(v - __half2float(h));
        size_t o = (size_t)(n0 + ty + j) * K + k0 + tx;
        Thi[o] = h;
        Tlo[o] = l;
    }
}

// ---------------------------------------------------------------------------
// fp16 2-pass mma GEMM, 3-stage cp.async pipeline, one barrier per iteration,
// 2 CTAs/SM (stage = 30 KB -> 3 stages = 92 KB/CTA).
// ---------------------------------------------------------------------------
#define ROWB     80
#define TILE_B   (128 * ROWB)                // 10240
#define STAGE_B  (3 * TILE_B)                // 30720
#define NSTAGE   3
#define SMEM_GEMM (NSTAGE * STAGE_B)         // 92160
#define NITER    (KDIM / 32)                 // 24

__global__ __launch_bounds__(256, 2) void gemm_mma(
    const __half* __restrict__ A,
    const __half* __restrict__ Bhi, const __half* __restrict__ Blo,
    float* __restrict__ C, int N, const float* __restrict__ bias)
{
    extern __shared__ char sm[];
    const int tid  = threadIdx.x;
    const int wid  = tid >> 5;
    const int lane = tid & 31;

    const size_t m0 = (size_t)blockIdx.y * 128;
    const size_t n0 = (size_t)blockIdx.x * 128;

    // ---- loader: 3 tiles x 64 threads ----
    const int ltile = tid >> 6;          // 0:A 1:Bhi 2:Blo 3:idle
    const int lsub  = tid & 63;
    const int lrow0 = lsub >> 2;
    const int lseg  = lsub & 3;
    const __half* lsrc;
    {
        const __half* s0 = A   + m0 * KDIM;
        const __half* s1 = Bhi + n0 * KDIM;
        const __half* s2 = Blo + n0 * KDIM;
        lsrc = (ltile == 0) ? s0 : (ltile == 1) ? s1 : s2;
    }
    const uint32_t sbase = smem_u32(sm);
    const uint32_t ldst0 = sbase + ltile * TILE_B + lrow0 * ROWB + lseg * 16;
    const __half* lsrc0 = lsrc + (size_t)lrow0 * KDIM + lseg * 8;

    auto load_stage = [&](int kc, int s) {
        if (ltile < 3) {
            uint32_t d = ldst0 + s * STAGE_B;
            const __half* g = lsrc0 + kc;
#pragma unroll
            for (int i = 0; i < 8; i++)
                CP16(d + i * 16 * ROWB, g + (size_t)i * 16 * KDIM);
        }
    };

    // ---- compute setup ----
    const int warp_m = wid & 1;
    const int warp_n = wid >> 1;
    const int g  = lane >> 3;
    const int r8 = lane & 7;
    const uint32_t a_off = (uint32_t)((warp_m * 64 + (g & 1) * 8 + r8) * ROWB + (g >> 1) * 16);
    const uint32_t b_off = (uint32_t)((warp_n * 32 + ((g >> 1) & 1) * 8 + r8) * ROWB + (g & 1) * 16);

    float acc[4][4][4];
#pragma unroll
    for (int i = 0; i < 4; i++)
#pragma unroll
        for (int j = 0; j < 4; j++)
#pragma unroll
            for (int q = 0; q < 4; q++) acc[i][j][q] = 0.f;

    // ---- prologue ----
    load_stage(0, 0);
    CP_COMMIT();
    load_stage(32, 1);
    CP_COMMIT();

    // ---- mainloop: ONE barrier per iteration ----
    for (int it = 0; it < NITER; it++) {
        CP_WAIT1();                   // stage it resident
        __syncthreads();              // stage (it-1)%3 fully consumed
        if (it + 2 < NITER)
            load_stage((it + 2) * 32, (it + 2) % NSTAGE);
        CP_COMMIT();                  // one group per iteration (may be empty)

        const uint32_t st = sbase + (it % NSTAGE) * STAGE_B;
#pragma unroll
        for (int kk = 0; kk < 2; kk++) {
            const uint32_t kb = kk * 32;
            uint32_t af[4][4], bh[4][2], bl[4][2];
#pragma unroll
            for (int mt = 0; mt < 4; mt++)
                ldsm4(af[mt], st + 0 * TILE_B + a_off + mt * 16 * ROWB + kb);
#pragma unroll
            for (int j = 0; j < 2; j++) {
                uint32_t t4[4];
                ldsm4(t4, st + 1 * TILE_B + b_off + j * 16 * ROWB + kb);
                bh[j * 2 + 0][0] = t4[0]; bh[j * 2 + 0][1] = t4[1];
                bh[j * 2 + 1][0] = t4[2]; bh[j * 2 + 1][1] = t4[3];
                ldsm4(t4, st + 2 * TILE_B + b_off + j * 16 * ROWB + kb);
                bl[j * 2 + 0][0] = t4[0]; bl[j * 2 + 0][1] = t4[1];
                bl[j * 2 + 1][0] = t4[2]; bl[j * 2 + 1][1] = t4[3];
            }
#pragma unroll
            for (int mt = 0; mt < 4; mt++)
#pragma unroll
                for (int nt = 0; nt < 4; nt++)
                    mma16816(acc[mt][nt], af[mt], bh[nt]);
#pragma unroll
            for (int mt = 0; mt < 4; mt++)
#pragma unroll
                for (int nt = 0; nt < 4; nt++)
                    mma16816(acc[mt][nt], af[mt], bl[nt]);
        }
    }

    // ---- epilogue ----
    const int crow = warp_m * 64 + (lane >> 2);
    const int ccol = warp_n * 32 + (lane & 3) * 2;
#pragma unroll
    for (int mt = 0; mt < 4; mt++) {
#pragma unroll
        for (int nt = 0; nt < 4; nt++) {
            float b0 = 0.f, b1 = 0.f;
            if (bias) {
                b0 = __ldg(bias + n0 + ccol + nt * 8);
                b1 = __ldg(bias + n0 + ccol + nt * 8 + 1);
            }
            float2 v0 = {acc[mt][nt][0] + b0, acc[mt][nt][1] + b1};
            float2 v1 = {acc[mt][nt][2] + b0, acc[mt][nt][3] + b1};
            float* p0 = C + (m0 + crow + mt * 16) * (size_t)N + n0 + ccol + nt * 8;
            float* p1 = p0 + 8 * (size_t)N;
            *(float2*)p0 = v0;
            *(float2*)p1 = v1;
        }
    }
}

// ---------------------------------------------------------------------------
// XCA phase 1: partial Gram + norms. grid (BH, SPLIT), 256 threads.
// ---------------------------------------------------------------------------
__global__ __launch_bounds__(256) void gram_kernel()
{
    __shared__ float qs[32][48];
    __shared__ float ks[32][48];

    const int bh = blockIdx.x;
    const int sp = blockIdx.y;
    const int b = bh >> 4;
    const int h = bh & 15;
    const float* base = g_qkv + (size_t)b * NTOK * (3 * CH) + (size_t)h * HD;
    const int tid = threadIdx.x;
    const int r = tid >> 4;
    const int c = tid & 15;

    float acc[3][3];
#pragma unroll
    for (int i = 0; i < 3; i++)
#pragma unroll
        for (int j = 0; j < 3; j++) acc[i][j] = 0.f;
    float ssq[3] = {0.f, 0.f, 0.f};
    float ssk[3] = {0.f, 0.f, 0.f};

    const int nstart = sp * TOKSP;
    for (int n0 = nstart; n0 < nstart + TOKSP; n0 += 32) {
        __syncthreads();
#pragma unroll
        for (int i = 0; i < 2; i++) {
            int idx = tid + i * 256;
            if (idx < 384) {
                int n = idx / 12;
                int m = (idx % 12) * 4;
                const float* p = base + (size_t)(n0 + n) * (3 * CH) + m;
                *(float4*)&qs[n][m] = *(const float4*)p;
                *(float4*)&ks[n][m] = *(const float4*)(p + CH);
            }
        }
        __syncthreads();
#pragma unroll 2
        for (int n = 0; n < 32; n++) {
            float q0 = qs[n][3 * r], q1 = qs[n][3 * r + 1], q2 = qs[n][3 * r + 2];
            float k0 = ks[n][3 * c], k1 = ks[n][3 * c + 1], k2 = ks[n][3 * c + 2];
            acc[0][0] = fmaf(q0, k0, acc[0][0]);
            acc[0][1] = fmaf(q0, k1, acc[0][1]);
            acc[0][2] = fmaf(q0, k2, acc[0][2]);
            acc[1][0] = fmaf(q1, k0, acc[1][0]);
            acc[1][1] = fmaf(q1, k1, acc[1][1]);
            acc[1][2] = fmaf(q1, k2, acc[1][2]);
            acc[2][0] = fmaf(q2, k0, acc[2][0]);
            acc[2][1] = fmaf(q2, k1, acc[2][1]);
            acc[2][2] = fmaf(q2, k2, acc[2][2]);
            if (c == 0) {
                ssq[0] = fmaf(q0, q0, ssq[0]);
                ssq[1] = fmaf(q1, q1, ssq[1]);
                ssq[2] = fmaf(q2, q2, ssq[2]);
            }
            if (r == 0) {
                ssk[0] = fmaf(k0, k0, ssk[0]);
                ssk[1] = fmaf(k1, k1, ssk[1]);
                ssk[2] = fmaf(k2, k2, ssk[2]);
            }
        }
    }

    float* gout = g_gram + ((size_t)bh * SPLIT + sp) * (HD * HD);
#pragma unroll
    for (int i = 0; i < 3; i++)
#pragma unroll
        for (int j = 0; j < 3; j++)
            gout[(3 * r + i) * HD + 3 * c + j] = acc[i][j];
    if (c == 0) {
        float* so = g_ssq + ((size_t)bh * SPLIT + sp) * HD;
#pragma unroll
        for (int i = 0; i < 3; i++) so[3 * r + i] = ssq[i];
    }
    if (r == 0) {
        float* so = g_ssk + ((size_t)bh * SPLIT + sp) * HD;
#pragma unroll
        for (int i = 0; i < 3; i++) so[3 * c + i] = ssk[i];
    }
}

// ---------------------------------------------------------------------------
// XCA phase 2: reduce partials, normalize, softmax. grid BH, 256 threads.
// ---------------------------------------------------------------------------
__global__ __launch_bounds__(256) void softmax_kernel(const float* __restrict__ temperature)
{
    __shared__ float attn[48][52];
    __shared__ float invq[48];
    __shared__ float invk[48];

    const int bh = blockIdx.x;
    const int h = bh & 15;
    const int tid = threadIdx.x;
    const int r = tid >> 4;
    const int c = tid & 15;

    // reduce norms
    if (tid < 48) {
        float s = 0.f;
#pragma unroll
        for (int p = 0; p < SPLIT; p++)
            s += g_ssq[((size_t)bh * SPLIT + p) * HD + tid];
        invq[tid] = 1.f / fmaxf(sqrtf(s), 1e-12f);
    } else if (tid < 96) {
        float s = 0.f;
#pragma unroll
        for (int p = 0; p < SPLIT; p++)
            s += g_ssk[((size_t)bh * SPLIT + p) * HD + tid - 48];
        invk[tid - 48] = 1.f / fmaxf(sqrtf(s), 1e-12f);
    }

    // reduce gram partials
    const float* gin = g_gram + (size_t)bh * SPLIT * (HD * HD);
    float sums[3][3];
#pragma unroll
    for (int i = 0; i < 3; i++)
#pragma unroll
        for (int j = 0; j < 3; j++) {
            float s = 0.f;
            int idx = (3 * r + i) * HD + 3 * c + j;
#pragma unroll
            for (int p = 0; p < SPLIT; p++)
                s += gin[p * (HD * HD) + idx];
            sums[i][j] = s;
        }
    __syncthreads();

    const float temp = temperature[h];
#pragma unroll
    for (int i = 0; i < 3; i++)
#pragma unroll
        for (int j = 0; j < 3; j++)
            attn[3 * r + i][3 * c + j] =
                sums[i][j] * invq[3 * r + i] * invk[3 * c + j] * temp;
    __syncthreads();

    const int lane = tid & 31;
    const int w = tid >> 5;
    for (int d = w; d < 48; d += 8) {
        float x1 = attn[d][lane];
        float x2 = (lane < 16) ? attn[d][32 + lane] : -1e30f;
        float m = fmaxf(x1, x2);
#pragma unroll
        for (int o = 16; o > 0; o >>= 1)
            m = fmaxf(m, __shfl_xor_sync(0xffffffffu, m, o));
        float p1 = expf(x1 - m);
        float p2 = (lane < 16) ? expf(x2 - m) : 0.f;
        float s = p1 + p2;
#pragma unroll
        for (int o = 16; o > 0; o >>= 1)
            s += __shfl_xor_sync(0xffffffffu, s, o);
        float inv = 1.f / s;
        attn[d][lane] = p1 * inv;
        if (lane < 16) attn[d][32 + lane] = p2 * inv;
    }
    __syncthreads();

    float* aout = g_attn + (size_t)bh * (HD * HD);
#pragma unroll
    for (int i = 0; i < 3; i++)
#pragma unroll
        for (int j = 0; j < 3; j++)
            aout[(3 * r + i) * HD + 3 * c + j] = attn[3 * r + i][3 * c + j];
}

// ---------------------------------------------------------------------------
// XCA phase 3: out = attn @ v, fp16 output. grid (BH, SPLIT), 256 threads.
// ---------------------------------------------------------------------------
__global__ __launch_bounds__(256) void av_kernel()
{
    __shared__ float attn[48 * 48];
    __shared__ float vs[16][48];

    const int bh = blockIdx.x;
    const int sp = blockIdx.y;
    const int b = bh >> 4;
    const int h = bh & 15;
    const float* vbase = g_qkv + (size_t)b * NTOK * (3 * CH) + (size_t)h * HD + 2 * CH;
    __half* outp = g_ah + (size_t)b * NTOK * CH + (size_t)h * HD;
    const int tid = threadIdx.x;

    const float* ain = g_attn + (size_t)bh * (HD * HD);
#pragma unroll
    for (int i = 0; i < 9; i++)
        attn[tid + i * 256] = ain[tid + i * 256];
    __syncthreads();

    const int d = tid % 48;
    const int vt = tid / 48;
    float areg[48];
    if (tid < 192) {
#pragma unroll
        for (int e = 0; e < 48; e++) areg[e] = attn[d * 48 + e];
    }

    const int nstart = sp * TOKSP;
    for (int n0 = nstart; n0 < nstart + TOKSP; n0 += 16) {
        __syncthreads();
        if (tid < 192) {
            int n = tid / 12;
            int m = (tid % 12) * 4;
            *(float4*)&vs[n][m] =
                *(const float4*)(vbase + (size_t)(n0 + n) * (3 * CH) + m);
        }
        __syncthreads();
        if (tid < 192) {
            int nb = vt * 4;
            float o0 = 0.f, o1 = 0.f, o2 = 0.f, o3 = 0.f;
#pragma unroll
            for (int e = 0; e < 48; e++) {
                float a = areg[e];
                o0 = fmaf(a, vs[nb + 0][e], o0);
                o1 = fmaf(a, vs[nb + 1][e], o1);
                o2 = fmaf(a, vs[nb + 2][e], o2);
                o3 = fmaf(a, vs[nb + 3][e], o3);
            }
            float ov[4] = {o0, o1, o2, o3};
#pragma unroll
            for (int j = 0; j < 4; j++)
                outp[(size_t)(n0 + nb + j) * CH + d] = __float2half_rn(ov[j]);
        }
    }
}

// ---------------------------------------------------------------------------
// Launch sequence
// ---------------------------------------------------------------------------
extern "C" void kernel_launch(void* const* d_in, const int* in_sizes, int n_in,
                              void* d_out, int out_size)
{
    const float* x           = (const float*)d_in[0];
    const float* qkv_w       = (const float*)d_in[1];
    const float* temperature = (const float*)d_in[2];
    const float* proj_w      = (const float*)d_in[3];
    const float* proj_b      = (const float*)d_in[4];
    float* out = (float*)d_out;

    __half *xh, *ah, *wqhi, *wqlo, *wphi, *wplo;
    float* qkv_d;
    cudaGetSymbolAddress((void**)&xh, g_xh);
    cudaGetSymbolAddress((void**)&ah, g_ah);
    cudaGetSymbolAddress((void**)&wqhi, g_wqhi);
    cudaGetSymbolAddress((void**)&wqlo, g_wqlo);
    cudaGetSymbolAddress((void**)&wphi, g_wphi);
    cudaGetSymbolAddress((void**)&wplo, g_wplo);
    cudaGetSymbolAddress((void**)&qkv_d, g_qkv);

    cudaFuncSetAttribute(gemm_mma, cudaFuncAttributeMaxDynamicSharedMemorySize, SMEM_GEMM);

    int n4 = MROWS * KDIM / 4;
    conv_kernel<<<(n4 + 255) / 256, 256>>>((const float4*)x, (__half2*)xh, n4);

    tsplit_kernel<<<dim3((3 * CH) / 32, KDIM / 32), dim3(32, 8)>>>(
        qkv_w, wqhi, wqlo, KDIM, 3 * CH);
    tsplit_kernel<<<dim3(CH / 32, KDIM / 32), dim3(32, 8)>>>(
        proj_w, wphi, wplo, KDIM, CH);

    gemm_mma<<<dim3((3 * CH) / 128, MROWS / 128), 256, SMEM_GEMM>>>(
        xh, wqhi, wqlo, qkv_d, 3 * CH, nullptr);

    gram_kernel<<<dim3(BH, SPLIT), 256>>>();
    softmax_kernel<<<BH, 256>>>(temperature);
    av_kernel<<<dim3(BH, SPLIT), 256>>>();

    gemm_mma<<<dim3(CH / 128, MROWS / 128), 256, SMEM_GEMM>>>(
        ah, wphi, wplo, out, CH, proj_b);
}

// round 7
// speedup vs baseline: 2.3711x; 1.3748x over previous
#include <cuda_runtime.h>
#include <cuda_fp16.h>
#include <math.h>
#include <stdint.h>
#include <stddef.h>

#define BATCH 16
#define NTOK  3136
#define CH    768
#define NH    16
#define HD    48
#define KDIM  768
#define MROWS (BATCH*NTOK)   // 50176
#define BH    (BATCH*NH)     // 256
#define SPLIT 7
#define TOKSP (NTOK/SPLIT)   // 448

// ----------------------------- device scratch ------------------------------
__device__ __half g_xh [(size_t)MROWS * KDIM];
__device__ float  g_qkv[(size_t)MROWS * 3 * CH];
__device__ __half g_ah [(size_t)MROWS * CH];
__device__ __half g_wq [(size_t)(3 * CH) * KDIM];
__device__ __half g_wp [(size_t)CH * KDIM];
__device__ float  g_gram[(size_t)BH * SPLIT * HD * HD];
__device__ float  g_ssq [(size_t)BH * SPLIT * HD];
__device__ float  g_ssk [(size_t)BH * SPLIT * HD];
__device__ float  g_attn[(size_t)BH * HD * HD];

// ----------------------------- PTX helpers ---------------------------------
__device__ __forceinline__ uint32_t smem_u32(const void* p) {
    return (uint32_t)__cvta_generic_to_shared(p);
}

__device__ __forceinline__ void mma16816(float* c, const uint32_t* a, const uint32_t* b) {
    asm volatile(
        "mma.sync.aligned.m16n8k16.row.col.f32.f16.f16.f32 "
        "{%0,%1,%2,%3}, {%4,%5,%6,%7}, {%8,%9}, {%0,%1,%2,%3};"
        : "+f"(c[0]), "+f"(c[1]), "+f"(c[2]), "+f"(c[3])
        : "r"(a[0]), "r"(a[1]), "r"(a[2]), "r"(a[3]), "r"(b[0]), "r"(b[1]));
}

__device__ __forceinline__ void ldsm4(uint32_t* r, uint32_t addr) {
    asm volatile("ldmatrix.sync.aligned.m8n8.x4.shared.b16 {%0,%1,%2,%3}, [%4];"
        : "=r"(r[0]), "=r"(r[1]), "=r"(r[2]), "=r"(r[3]) : "r"(addr));
}

#define CP16(dst, src) \
    asm volatile("cp.async.cg.shared.global [%0], [%1], 16;" :: "r"(dst), "l"(src))
#define CP_COMMIT()  asm volatile("cp.async.commit_group;" ::: "memory")
#define CP_WAIT2()   asm volatile("cp.async.wait_group 2;" ::: "memory")

// ---------------------------------------------------------------------------
// fp32 -> fp16 convert
// ---------------------------------------------------------------------------
__global__ void conv_kernel(const float4* __restrict__ in,
                            __half2* __restrict__ out, int n4)
{
    int i = blockIdx.x * blockDim.x + threadIdx.x;
    if (i >= n4) return;
    float4 v = in[i];
    out[2 * i + 0] = __floats2half2_rn(v.x, v.y);
    out[2 * i + 1] = __floats2half2_rn(v.z, v.w);
}

// ---------------------------------------------------------------------------
// Transpose + convert: W[K,N] fp32 -> Wt [N,K] fp16
// ---------------------------------------------------------------------------
__global__ void tconv_kernel(const float* __restrict__ W,
                             __half* __restrict__ T, int K, int N)
{
    __shared__ float tile[32][33];
    int n0 = blockIdx.x * 32, k0 = blockIdx.y * 32;
    int tx = threadIdx.x, ty = threadIdx.y;   // 32 x 8
#pragma unroll
    for (int j = 0; j < 32; j += 8)
        tile[ty + j][tx] = W[(size_t)(k0 + ty + j) * N + n0 + tx];
    __syncthreads();
#pragma unroll
    for (int j = 0; j < 32; j += 8)
        T[(size_t)(n0 + ty + j) * K + k0 + tx] = __float2half_rn(tile[tx][ty + j]);
}

// ---------------------------------------------------------------------------
// Single-pass fp16 mma GEMM: C[M,N] = A*B^T (+bias), fp32 accumulate.
// CTA tile 128x128, K-chunk 32, FOUR-stage cp.async pipeline, one barrier
// per iteration, 2 CTAs/SM (stage = 20 KB -> 4 stages = 80 KB/CTA).
// SMEM rows padded to 80B: conflict-free ldmatrix/cp.async.
// ---------------------------------------------------------------------------
#define ROWB     80
#define TILE_B   (128 * ROWB)                // 10240
#define STAGE_B  (2 * TILE_B)                // A, B = 20480
#define NSTAGE   4
#define SMEM_GEMM (NSTAGE * STAGE_B)         // 81920
#define NITER    (KDIM / 32)                 // 24

__global__ __launch_bounds__(256, 2) void gemm_mma(
    const __half* __restrict__ A, const __half* __restrict__ B,
    float* __restrict__ C, int N, const float* __restrict__ bias)
{
    extern __shared__ char sm[];
    const int tid  = threadIdx.x;
    const int wid  = tid >> 5;
    const int lane = tid & 31;

    const size_t m0 = (size_t)blockIdx.y * 128;
    const size_t n0 = (size_t)blockIdx.x * 128;

    // ---- loader: 2 tiles x 128 threads, 4 x 16B chunks per thread ----
    const int ltile = tid >> 7;          // 0:A 1:B
    const int lsub  = tid & 127;
    const int lrow0 = lsub >> 2;         // 0..31, + i*32
    const int lseg  = lsub & 3;
    const __half* lsrc = (ltile == 0) ? A + m0 * KDIM : B + n0 * KDIM;
    const uint32_t sbase = smem_u32(sm);
    const uint32_t ldst0 = sbase + ltile * TILE_B + lrow0 * ROWB + lseg * 16;
    const __half* lsrc0 = lsrc + (size_t)lrow0 * KDIM + lseg * 8;

    auto load_stage = [&](int kc, int s) {
        uint32_t d = ldst0 + s * STAGE_B;
        const __half* g = lsrc0 + kc;
#pragma unroll
        for (int i = 0; i < 4; i++)
            CP16(d + i * 32 * ROWB, g + (size_t)i * 32 * KDIM);
    };

    // ---- compute setup: 8 warps, warp tile 64x32 ----
    const int warp_m = wid & 1;
    const int warp_n = wid >> 1;
    const int g  = lane >> 3;
    const int r8 = lane & 7;
    const uint32_t a_off = (uint32_t)((warp_m * 64 + (g & 1) * 8 + r8) * ROWB + (g >> 1) * 16);
    const uint32_t b_off = (uint32_t)((warp_n * 32 + ((g >> 1) & 1) * 8 + r8) * ROWB + (g & 1) * 16);

    float acc[4][4][4];
#pragma unroll
    for (int i = 0; i < 4; i++)
#pragma unroll
        for (int j = 0; j < 4; j++)
#pragma unroll
            for (int q = 0; q < 4; q++) acc[i][j][q] = 0.f;

    // ---- prologue: fill stages 0..2 ----
    load_stage(0, 0);
    CP_COMMIT();
    load_stage(32, 1);
    CP_COMMIT();
    load_stage(64, 2);
    CP_COMMIT();

    // ---- mainloop: ONE barrier per iteration ----
    for (int it = 0; it < NITER; it++) {
        CP_WAIT2();                   // stage it resident (<=2 groups pending)
        __syncthreads();              // stage (it-1)%4 fully consumed
        if (it + 3 < NITER)
            load_stage((it + 3) * 32, (it + 3) % NSTAGE);
        CP_COMMIT();                  // one group per iteration (may be empty)

        const uint32_t st = sbase + (it % NSTAGE) * STAGE_B;
#pragma unroll
        for (int kk = 0; kk < 2; kk++) {
            const uint32_t kb = kk * 32;
            uint32_t af[4][4], bf[4][2];
#pragma unroll
            for (int mt = 0; mt < 4; mt++)
                ldsm4(af[mt], st + 0 * TILE_B + a_off + mt * 16 * ROWB + kb);
#pragma unroll
            for (int j = 0; j < 2; j++) {
                uint32_t t4[4];
                ldsm4(t4, st + 1 * TILE_B + b_off + j * 16 * ROWB + kb);
                bf[j * 2 + 0][0] = t4[0]; bf[j * 2 + 0][1] = t4[1];
                bf[j * 2 + 1][0] = t4[2]; bf[j * 2 + 1][1] = t4[3];
            }
#pragma unroll
            for (int mt = 0; mt < 4; mt++)
#pragma unroll
                for (int nt = 0; nt < 4; nt++)
                    mma16816(acc[mt][nt], af[mt], bf[nt]);
        }
    }

    // ---- epilogue ----
    const int crow = warp_m * 64 + (lane >> 2);
    const int ccol = warp_n * 32 + (lane & 3) * 2;
#pragma unroll
    for (int mt = 0; mt < 4; mt++) {
#pragma unroll
        for (int nt = 0; nt < 4; nt++) {
            float b0 = 0.f, b1 = 0.f;
            if (bias) {
                b0 = __ldg(bias + n0 + ccol + nt * 8);
                b1 = __ldg(bias + n0 + ccol + nt * 8 + 1);
            }
            float2 v0 = {acc[mt][nt][0] + b0, acc[mt][nt][1] + b1};
            float2 v1 = {acc[mt][nt][2] + b0, acc[mt][nt][3] + b1};
            float* p0 = C + (m0 + crow + mt * 16) * (size_t)N + n0 + ccol + nt * 8;
            float* p1 = p0 + 8 * (size_t)N;
            *(float2*)p0 = v0;
            *(float2*)p1 = v1;
        }
    }
}

// ---------------------------------------------------------------------------
// XCA phase 1: partial Gram + norms. grid (BH, SPLIT), 256 threads.
// ---------------------------------------------------------------------------
__global__ __launch_bounds__(256) void gram_kernel()
{
    __shared__ float qs[32][48];
    __shared__ float ks[32][48];

    const int bh = blockIdx.x;
    const int sp = blockIdx.y;
    const int b = bh >> 4;
    const int h = bh & 15;
    const float* base = g_qkv + (size_t)b * NTOK * (3 * CH) + (size_t)h * HD;
    const int tid = threadIdx.x;
    const int r = tid >> 4;
    const int c = tid & 15;

    float acc[3][3];
#pragma unroll
    for (int i = 0; i < 3; i++)
#pragma unroll
        for (int j = 0; j < 3; j++) acc[i][j] = 0.f;
    float ssq[3] = {0.f, 0.f, 0.f};
    float ssk[3] = {0.f, 0.f, 0.f};

    const int nstart = sp * TOKSP;
    for (int n0 = nstart; n0 < nstart + TOKSP; n0 += 32) {
        __syncthreads();
#pragma unroll
        for (int i = 0; i < 2; i++) {
            int idx = tid + i * 256;
            if (idx < 384) {
                int n = idx / 12;
                int m = (idx % 12) * 4;
                const float* p = base + (size_t)(n0 + n) * (3 * CH) + m;
                *(float4*)&qs[n][m] = *(const float4*)p;
                *(float4*)&ks[n][m] = *(const float4*)(p + CH);
            }
        }
        __syncthreads();
#pragma unroll 2
        for (int n = 0; n < 32; n++) {
            float q0 = qs[n][3 * r], q1 = qs[n][3 * r + 1], q2 = qs[n][3 * r + 2];
            float k0 = ks[n][3 * c], k1 = ks[n][3 * c + 1], k2 = ks[n][3 * c + 2];
            acc[0][0] = fmaf(q0, k0, acc[0][0]);
            acc[0][1] = fmaf(q0, k1, acc[0][1]);
            acc[0][2] = fmaf(q0, k2, acc[0][2]);
            acc[1][0] = fmaf(q1, k0, acc[1][0]);
            acc[1][1] = fmaf(q1, k1, acc[1][1]);
            acc[1][2] = fmaf(q1, k2, acc[1][2]);
            acc[2][0] = fmaf(q2, k0, acc[2][0]);
            acc[2][1] = fmaf(q2, k1, acc[2][1]);
            acc[2][2] = fmaf(q2, k2, acc[2][2]);
            if (c == 0) {
                ssq[0] = fmaf(q0, q0, ssq[0]);
                ssq[1] = fmaf(q1, q1, ssq[1]);
                ssq[2] = fmaf(q2, q2, ssq[2]);
            }
            if (r == 0) {
                ssk[0] = fmaf(k0, k0, ssk[0]);
                ssk[1] = fmaf(k1, k1, ssk[1]);
                ssk[2] = fmaf(k2, k2, ssk[2]);
            }
        }
    }

    float* gout = g_gram + ((size_t)bh * SPLIT + sp) * (HD * HD);
#pragma unroll
    for (int i = 0; i < 3; i++)
#pragma unroll
        for (int j = 0; j < 3; j++)
            gout[(3 * r + i) * HD + 3 * c + j] = acc[i][j];
    if (c == 0) {
        float* so = g_ssq + ((size_t)bh * SPLIT + sp) * HD;
#pragma unroll
        for (int i = 0; i < 3; i++) so[3 * r + i] = ssq[i];
    }
    if (r == 0) {
        float* so = g_ssk + ((size_t)bh * SPLIT + sp) * HD;
#pragma unroll
        for (int i = 0; i < 3; i++) so[3 * c + i] = ssk[i];
    }
}

// ---------------------------------------------------------------------------
// XCA phase 2: reduce partials, normalize, softmax. grid BH, 256 threads.
// ---------------------------------------------------------------------------
__global__ __launch_bounds__(256) void softmax_kernel(const float* __restrict__ temperature)
{
    __shared__ float attn[48][52];
    __shared__ float invq[48];
    __shared__ float invk[48];

    const int bh = blockIdx.x;
    const int h = bh & 15;
    const int tid = threadIdx.x;
    const int r = tid >> 4;
    const int c = tid & 15;

    if (tid < 48) {
        float s = 0.f;
#pragma unroll
        for (int p = 0; p < SPLIT; p++)
            s += g_ssq[((size_t)bh * SPLIT + p) * HD + tid];
        invq[tid] = 1.f / fmaxf(sqrtf(s), 1e-12f);
    } else if (tid < 96) {
        float s = 0.f;
#pragma unroll
        for (int p = 0; p < SPLIT; p++)
            s += g_ssk[((size_t)bh * SPLIT + p) * HD + tid - 48];
        invk[tid - 48] = 1.f / fmaxf(sqrtf(s), 1e-12f);
    }

    const float* gin = g_gram + (size_t)bh * SPLIT * (HD * HD);
    float sums[3][3];
#pragma unroll
    for (int i = 0; i < 3; i++)
#pragma unroll
        for (int j = 0; j < 3; j++) {
            float s = 0.f;
            int idx = (3 * r + i) * HD + 3 * c + j;
#pragma unroll
            for (int p = 0; p < SPLIT; p++)
                s += gin[p * (HD * HD) + idx];
            sums[i][j] = s;
        }
    __syncthreads();

    const float temp = temperature[h];
#pragma unroll
    for (int i = 0; i < 3; i++)
#pragma unroll
        for (int j = 0; j < 3; j++)
            attn[3 * r + i][3 * c + j] =
                sums[i][j] * invq[3 * r + i] * invk[3 * c + j] * temp;
    __syncthreads();

    const int lane = tid & 31;
    const int w = tid >> 5;
    for (int d = w; d < 48; d += 8) {
        float x1 = attn[d][lane];
        float x2 = (lane < 16) ? attn[d][32 + lane] : -1e30f;
        float m = fmaxf(x1, x2);
#pragma unroll
        for (int o = 16; o > 0; o >>= 1)
            m = fmaxf(m, __shfl_xor_sync(0xffffffffu, m, o));
        float p1 = expf(x1 - m);
        float p2 = (lane < 16) ? expf(x2 - m) : 0.f;
        float s = p1 + p2;
#pragma unroll
        for (int o = 16; o > 0; o >>= 1)
            s += __shfl_xor_sync(0xffffffffu, s, o);
        float inv = 1.f / s;
        attn[d][lane] = p1 * inv;
        if (lane < 16) attn[d][32 + lane] = p2 * inv;
    }
    __syncthreads();

    float* aout = g_attn + (size_t)bh * (HD * HD);
#pragma unroll
    for (int i = 0; i < 3; i++)
#pragma unroll
        for (int j = 0; j < 3; j++)
            aout[(3 * r + i) * HD + 3 * c + j] = attn[3 * r + i][3 * c + j];
}

// ---------------------------------------------------------------------------
// XCA phase 3: out = attn @ v, fp16 output. grid (BH, SPLIT), 256 threads.
// ---------------------------------------------------------------------------
__global__ __launch_bounds__(256) void av_kernel()
{
    __shared__ float attn[48 * 48];
    __shared__ float vs[16][48];

    const int bh = blockIdx.x;
    const int sp = blockIdx.y;
    const int b = bh >> 4;
    const int h = bh & 15;
    const float* vbase = g_qkv + (size_t)b * NTOK * (3 * CH) + (size_t)h * HD + 2 * CH;
    __half* outp = g_ah + (size_t)b * NTOK * CH + (size_t)h * HD;
    const int tid = threadIdx.x;

    const float* ain = g_attn + (size_t)bh * (HD * HD);
#pragma unroll
    for (int i = 0; i < 9; i++)
        attn[tid + i * 256] = ain[tid + i * 256];
    __syncthreads();

    const int d = tid % 48;
    const int vt = tid / 48;
    float areg[48];
    if (tid < 192) {
#pragma unroll
        for (int e = 0; e < 48; e++) areg[e] = attn[d * 48 + e];
    }

    const int nstart = sp * TOKSP;
    for (int n0 = nstart; n0 < nstart + TOKSP; n0 += 16) {
        __syncthreads();
        if (tid < 192) {
            int n = tid / 12;
            int m = (tid % 12) * 4;
            *(float4*)&vs[n][m] =
                *(const float4*)(vbase + (size_t)(n0 + n) * (3 * CH) + m);
        }
        __syncthreads();
        if (tid < 192) {
            int nb = vt * 4;
            float o0 = 0.f, o1 = 0.f, o2 = 0.f, o3 = 0.f;
#pragma unroll
            for (int e = 0; e < 48; e++) {
                float a = areg[e];
                o0 = fmaf(a, vs[nb + 0][e], o0);
                o1 = fmaf(a, vs[nb + 1][e], o1);
                o2 = fmaf(a, vs[nb + 2][e], o2);
                o3 = fmaf(a, vs[nb + 3][e], o3);
            }
            float ov[4] = {o0, o1, o2, o3};
#pragma unroll
            for (int j = 0; j < 4; j++)
                outp[(size_t)(n0 + nb + j) * CH + d] = __float2half_rn(ov[j]);
        }
    }
}

// ---------------------------------------------------------------------------
// Launch sequence
// ---------------------------------------------------------------------------
extern "C" void kernel_launch(void* const* d_in, const int* in_sizes, int n_in,
                              void* d_out, int out_size)
{
    const float* x           = (const float*)d_in[0];
    const float* qkv_w       = (const float*)d_in[1];
    const float* temperature = (const float*)d_in[2];
    const float* proj_w      = (const float*)d_in[3];
    const float* proj_b      = (const float*)d_in[4];
    float* out = (float*)d_out;

    __half *xh, *ah, *wq, *wp;
    float* qkv_d;
    cudaGetSymbolAddress((void**)&xh, g_xh);
    cudaGetSymbolAddress((void**)&ah, g_ah);
    cudaGetSymbolAddress((void**)&wq, g_wq);
    cudaGetSymbolAddress((void**)&wp, g_wp);
    cudaGetSymbolAddress((void**)&qkv_d, g_qkv);

    cudaFuncSetAttribute(gemm_mma, cudaFuncAttributeMaxDynamicSharedMemorySize, SMEM_GEMM);

    int n4 = MROWS * KDIM / 4;
    conv_kernel<<<(n4 + 255) / 256, 256>>>((const float4*)x, (__half2*)xh, n4);

    tconv_kernel<<<dim3((3 * CH) / 32, KDIM / 32), dim3(32, 8)>>>(
        qkv_w, wq, KDIM, 3 * CH);
    tconv_kernel<<<dim3(CH / 32, KDIM / 32), dim3(32, 8)>>>(
        proj_w, wp, KDIM, CH);

    gemm_mma<<<dim3((3 * CH) / 128, MROWS / 128), 256, SMEM_GEMM>>>(
        xh, wq, qkv_d, 3 * CH, nullptr);

    gram_kernel<<<dim3(BH, SPLIT), 256>>>();
    softmax_kernel<<<BH, 256>>>(temperature);
    av_kernel<<<dim3(BH, SPLIT), 256>>>();

    gemm_mma<<<dim3(CH / 128, MROWS / 128), 256, SMEM_GEMM>>>(
        ah, wp, out, CH, proj_b);
}

// round 8
// speedup vs baseline: 3.2544x; 1.3725x over previous
#include <cuda_runtime.h>
#include <cuda_fp16.h>
#include <math.h>
#include <stdint.h>
#include <stddef.h>

#define BATCH 16
#define NTOK  3136
#define CH    768
#define NH    16
#define HD    48
#define KDIM  768
#define MROWS (BATCH*NTOK)   // 50176
#define BH    (BATCH*NH)     // 256
#define SPLIT 7
#define TOKSP (NTOK/SPLIT)   // 448

// ----------------------------- device scratch ------------------------------
__device__ __half g_xh  [(size_t)MROWS * KDIM];
__device__ __half g_qT  [(size_t)BH * HD * NTOK];   // [bh][d][n] fp16
__device__ __half g_kT  [(size_t)BH * HD * NTOK];
__device__ __half g_v   [(size_t)MROWS * CH];       // [token][h*48+d] fp16
__device__ __half g_ah  [(size_t)MROWS * CH];
__device__ __half g_wq  [(size_t)(3 * CH) * KDIM];
__device__ __half g_wp  [(size_t)CH * KDIM];
__device__ float  g_gram[(size_t)BH * SPLIT * HD * HD];
__device__ float  g_ssq [(size_t)BH * SPLIT * HD];
__device__ float  g_ssk [(size_t)BH * SPLIT * HD];
__device__ __half g_attnh[(size_t)BH * HD * HD];

// ----------------------------- PTX helpers ---------------------------------
__device__ __forceinline__ uint32_t smem_u32(const void* p) {
    return (uint32_t)__cvta_generic_to_shared(p);
}

__device__ __forceinline__ void mma16816(float* c, const uint32_t* a, const uint32_t* b) {
    asm volatile(
        "mma.sync.aligned.m16n8k16.row.col.f32.f16.f16.f32 "
        "{%0,%1,%2,%3}, {%4,%5,%6,%7}, {%8,%9}, {%0,%1,%2,%3};"
        : "+f"(c[0]), "+f"(c[1]), "+f"(c[2]), "+f"(c[3])
        : "r"(a[0]), "r"(a[1]), "r"(a[2]), "r"(a[3]), "r"(b[0]), "r"(b[1]));
}

__device__ __forceinline__ void ldsm4(uint32_t* r, uint32_t addr) {
    asm volatile("ldmatrix.sync.aligned.m8n8.x4.shared.b16 {%0,%1,%2,%3}, [%4];"
        : "=r"(r[0]), "=r"(r[1]), "=r"(r[2]), "=r"(r[3]) : "r"(addr));
}

#define CP16(dst, src) \
    asm volatile("cp.async.cg.shared.global [%0], [%1], 16;" :: "r"(dst), "l"(src))
#define CP_COMMIT()  asm volatile("cp.async.commit_group;" ::: "memory")
#define CP_WAIT0()   asm volatile("cp.async.wait_group 0;" ::: "memory")
#define CP_WAIT1()   asm volatile("cp.async.wait_group 1;" ::: "memory")
#define CP_WAIT2()   asm volatile("cp.async.wait_group 2;" ::: "memory")

// ---------------------------------------------------------------------------
// fp32 -> fp16 convert
// ---------------------------------------------------------------------------
__global__ void conv_kernel(const float4* __restrict__ in,
                            __half2* __restrict__ out, int n4)
{
    int i = blockIdx.x * blockDim.x + threadIdx.x;
    if (i >= n4) return;
    float4 v = in[i];
    out[2 * i + 0] = __floats2half2_rn(v.x, v.y);
    out[2 * i + 1] = __floats2half2_rn(v.z, v.w);
}

// ---------------------------------------------------------------------------
// Transpose + convert: W[K,N] fp32 -> Wt [N,K] fp16
// ---------------------------------------------------------------------------
__global__ void tconv_kernel(const float* __restrict__ W,
                             __half* __restrict__ T, int K, int N)
{
    __shared__ float tile[32][33];
    int n0 = blockIdx.x * 32, k0 = blockIdx.y * 32;
    int tx = threadIdx.x, ty = threadIdx.y;   // 32 x 8
#pragma unroll
    for (int j = 0; j < 32; j += 8)
        tile[ty + j][tx] = W[(size_t)(k0 + ty + j) * N + n0 + tx];
    __syncthreads();
#pragma unroll
    for (int j = 0; j < 32; j += 8)
        T[(size_t)(n0 + ty + j) * K + k0 + tx] = __float2half_rn(tile[tx][ty + j]);
}

// ---------------------------------------------------------------------------
// GEMM common geometry
// ---------------------------------------------------------------------------
#define ROWB     80
#define TILE_B   (128 * ROWB)                // 10240
#define STAGE_B  (2 * TILE_B)                // 20480
#define NSTAGE   4
#define SMEM_GEMM (NSTAGE * STAGE_B)         // 81920
#define NITER    (KDIM / 32)                 // 24

// ---------------------------------------------------------------------------
// GEMM1: qkv = x @ qkv_w^T, fp16 outputs in XCA layouts.
//   q section -> g_qT [bh][d][n] (transposed via smem)
//   k section -> g_kT likewise
//   v section -> g_v  [token][h*48+d]
// ---------------------------------------------------------------------------
__global__ __launch_bounds__(256, 2) void gemm_qkv(
    const __half* __restrict__ A, const __half* __restrict__ B,
    __half* __restrict__ Qt, __half* __restrict__ Kt, __half* __restrict__ Vp)
{
    extern __shared__ char sm[];
    const int tid  = threadIdx.x;
    const int wid  = tid >> 5;
    const int lane = tid & 31;

    const size_t m0 = (size_t)blockIdx.y * 128;
    const size_t n0 = (size_t)blockIdx.x * 128;

    const int ltile = tid >> 7;
    const int lsub  = tid & 127;
    const int lrow0 = lsub >> 2;
    const int lseg  = lsub & 3;
    const __half* lsrc = (ltile == 0) ? A + m0 * KDIM : B + n0 * KDIM;
    const uint32_t sbase = smem_u32(sm);
    const uint32_t ldst0 = sbase + ltile * TILE_B + lrow0 * ROWB + lseg * 16;
    const __half* lsrc0 = lsrc + (size_t)lrow0 * KDIM + lseg * 8;

    auto load_stage = [&](int kc, int s) {
        uint32_t d = ldst0 + s * STAGE_B;
        const __half* g = lsrc0 + kc;
#pragma unroll
        for (int i = 0; i < 4; i++)
            CP16(d + i * 32 * ROWB, g + (size_t)i * 32 * KDIM);
    };

    const int warp_m = wid & 1;
    const int warp_n = wid >> 1;
    const int g  = lane >> 3;
    const int r8 = lane & 7;
    const uint32_t a_off = (uint32_t)((warp_m * 64 + (g & 1) * 8 + r8) * ROWB + (g >> 1) * 16);
    const uint32_t b_off = (uint32_t)((warp_n * 32 + ((g >> 1) & 1) * 8 + r8) * ROWB + (g & 1) * 16);

    float acc[4][4][4];
#pragma unroll
    for (int i = 0; i < 4; i++)
#pragma unroll
        for (int j = 0; j < 4; j++)
#pragma unroll
            for (int q = 0; q < 4; q++) acc[i][j][q] = 0.f;

    load_stage(0, 0);  CP_COMMIT();
    load_stage(32, 1); CP_COMMIT();
    load_stage(64, 2); CP_COMMIT();

    for (int it = 0; it < NITER; it++) {
        CP_WAIT2();
        __syncthreads();
        if (it + 3 < NITER)
            load_stage((it + 3) * 32, (it + 3) % NSTAGE);
        CP_COMMIT();

        const uint32_t st = sbase + (it % NSTAGE) * STAGE_B;
#pragma unroll
        for (int kk = 0; kk < 2; kk++) {
            const uint32_t kb = kk * 32;
            uint32_t af[4][4], bf[4][2];
#pragma unroll
            for (int mt = 0; mt < 4; mt++)
                ldsm4(af[mt], st + 0 * TILE_B + a_off + mt * 16 * ROWB + kb);
#pragma unroll
            for (int j = 0; j < 2; j++) {
                uint32_t t4[4];
                ldsm4(t4, st + 1 * TILE_B + b_off + j * 16 * ROWB + kb);
                bf[j * 2 + 0][0] = t4[0]; bf[j * 2 + 0][1] = t4[1];
                bf[j * 2 + 1][0] = t4[2]; bf[j * 2 + 1][1] = t4[3];
            }
#pragma unroll
            for (int mt = 0; mt < 4; mt++)
#pragma unroll
                for (int nt = 0; nt < 4; nt++)
                    mma16816(acc[mt][nt], af[mt], bf[nt]);
        }
    }

    // ---- epilogue ----
    CP_WAIT0();
    __syncthreads();   // all smem reads done; safe to reuse sm
    const int section = (int)(n0 / 768);   // 0:q 1:k 2:v
    const int crow = warp_m * 64 + (lane >> 2);
    const int ccol = warp_n * 32 + (lane & 3) * 2;

    if (section == 2) {
#pragma unroll
        for (int mt = 0; mt < 4; mt++) {
#pragma unroll
            for (int nt = 0; nt < 4; nt++) {
                size_t row = m0 + crow + mt * 16;
                int vc = (int)(n0 - 1536) + ccol + nt * 8;
                __half2 h0 = __floats2half2_rn(acc[mt][nt][0], acc[mt][nt][1]);
                __half2 h1 = __floats2half2_rn(acc[mt][nt][2], acc[mt][nt][3]);
                *(__half2*)(Vp + row * CH + vc) = h0;
                *(__half2*)(Vp + (row + 8) * CH + vc) = h1;
            }
        }
    } else {
        // transpose through smem: layout [col 128][token 128], row stride 272B
#pragma unroll
        for (int mt = 0; mt < 4; mt++) {
#pragma unroll
            for (int nt = 0; nt < 4; nt++) {
                int col = ccol + nt * 8;
                int row = crow + mt * 16;
                *(__half*)(sm + (size_t)col * 272 + row * 2)             = __float2half_rn(acc[mt][nt][0]);
                *(__half*)(sm + (size_t)(col + 1) * 272 + row * 2)       = __float2half_rn(acc[mt][nt][1]);
                *(__half*)(sm + (size_t)col * 272 + (row + 8) * 2)       = __float2half_rn(acc[mt][nt][2]);
                *(__half*)(sm + (size_t)(col + 1) * 272 + (row + 8) * 2) = __float2half_rn(acc[mt][nt][3]);
            }
        }
        __syncthreads();
        __half* dst = (section == 0) ? Qt : Kt;
        const int base_gc = (int)n0 - section * 768;
#pragma unroll
        for (int i = 0; i < 8; i++) {
            int idx = tid + i * 256;          // 0..2047
            int col = idx >> 4, tv = idx & 15;
            uint4 val = *(uint4*)(sm + (size_t)col * 272 + tv * 16);
            int gc = base_gc + col;
            int hh = gc / 48, dd = gc - hh * 48;
            size_t tok = m0 + tv * 8;
            int b = (int)(tok / NTOK);
            int n = (int)(tok - (size_t)b * NTOK);
            *(uint4*)(dst + ((size_t)(b * 16 + hh) * HD + dd) * NTOK + n) = val;
        }
    }
}

// ---------------------------------------------------------------------------
// GEMM2: out = att @ proj_w^T + bias, fp32 out.
// ---------------------------------------------------------------------------
__global__ __launch_bounds__(256, 2) void gemm_mma(
    const __half* __restrict__ A, const __half* __restrict__ B,
    float* __restrict__ C, int N, const float* __restrict__ bias)
{
    extern __shared__ char sm[];
    const int tid  = threadIdx.x;
    const int wid  = tid >> 5;
    const int lane = tid & 31;

    const size_t m0 = (size_t)blockIdx.y * 128;
    const size_t n0 = (size_t)blockIdx.x * 128;

    const int ltile = tid >> 7;
    const int lsub  = tid & 127;
    const int lrow0 = lsub >> 2;
    const int lseg  = lsub & 3;
    const __half* lsrc = (ltile == 0) ? A + m0 * KDIM : B + n0 * KDIM;
    const uint32_t sbase = smem_u32(sm);
    const uint32_t ldst0 = sbase + ltile * TILE_B + lrow0 * ROWB + lseg * 16;
    const __half* lsrc0 = lsrc + (size_t)lrow0 * KDIM + lseg * 8;

    auto load_stage = [&](int kc, int s) {
        uint32_t d = ldst0 + s * STAGE_B;
        const __half* g = lsrc0 + kc;
#pragma unroll
        for (int i = 0; i < 4; i++)
            CP16(d + i * 32 * ROWB, g + (size_t)i * 32 * KDIM);
    };

    const int warp_m = wid & 1;
    const int warp_n = wid >> 1;
    const int g  = lane >> 3;
    const int r8 = lane & 7;
    const uint32_t a_off = (uint32_t)((warp_m * 64 + (g & 1) * 8 + r8) * ROWB + (g >> 1) * 16);
    const uint32_t b_off = (uint32_t)((warp_n * 32 + ((g >> 1) & 1) * 8 + r8) * ROWB + (g & 1) * 16);

    float acc[4][4][4];
#pragma unroll
    for (int i = 0; i < 4; i++)
#pragma unroll
        for (int j = 0; j < 4; j++)
#pragma unroll
            for (int q = 0; q < 4; q++) acc[i][j][q] = 0.f;

    load_stage(0, 0);  CP_COMMIT();
    load_stage(32, 1); CP_COMMIT();
    load_stage(64, 2); CP_COMMIT();

    for (int it = 0; it < NITER; it++) {
        CP_WAIT2();
        __syncthreads();
        if (it + 3 < NITER)
            load_stage((it + 3) * 32, (it + 3) % NSTAGE);
        CP_COMMIT();

        const uint32_t st = sbase + (it % NSTAGE) * STAGE_B;
#pragma unroll
        for (int kk = 0; kk < 2; kk++) {
            const uint32_t kb = kk * 32;
            uint32_t af[4][4], bf[4][2];
#pragma unroll
            for (int mt = 0; mt < 4; mt++)
                ldsm4(af[mt], st + 0 * TILE_B + a_off + mt * 16 * ROWB + kb);
#pragma unroll
            for (int j = 0; j < 2; j++) {
                uint32_t t4[4];
                ldsm4(t4, st + 1 * TILE_B + b_off + j * 16 * ROWB + kb);
                bf[j * 2 + 0][0] = t4[0]; bf[j * 2 + 0][1] = t4[1];
                bf[j * 2 + 1][0] = t4[2]; bf[j * 2 + 1][1] = t4[3];
            }
#pragma unroll
            for (int mt = 0; mt < 4; mt++)
#pragma unroll
                for (int nt = 0; nt < 4; nt++)
                    mma16816(acc[mt][nt], af[mt], bf[nt]);
        }
    }

    const int crow = warp_m * 64 + (lane >> 2);
    const int ccol = warp_n * 32 + (lane & 3) * 2;
#pragma unroll
    for (int mt = 0; mt < 4; mt++) {
#pragma unroll
        for (int nt = 0; nt < 4; nt++) {
            float b0 = __ldg(bias + n0 + ccol + nt * 8);
            float b1 = __ldg(bias + n0 + ccol + nt * 8 + 1);
            float2 v0 = {acc[mt][nt][0] + b0, acc[mt][nt][1] + b1};
            float2 v1 = {acc[mt][nt][2] + b0, acc[mt][nt][3] + b1};
            float* p0 = C + (m0 + crow + mt * 16) * (size_t)N + n0 + ccol + nt * 8;
            float* p1 = p0 + 8 * (size_t)N;
            *(float2*)p0 = v0;
            *(float2*)p1 = v1;
        }
    }
}

// ---------------------------------------------------------------------------
// Gram via mma: per (bh, split) partial gram 48x48 + partial ssq/ssk.
// A = qT rows (d, token-major), B = kT rows (e, token-major), K = 448 tokens.
// Warps 0-3: mma, k16-sliced; warps 4-7: norm sums from the same smem tiles.
// ---------------------------------------------------------------------------
#define GROWB  144                 // 64 fp16 = 128B data + 16B pad
#define GTILE  (48 * GROWB)        // 6912
#define GSTAGE (2 * GTILE)         // 13824
#define GRED   (2 * GSTAGE)        // red buffer offset = 27648
#define SMEM_GRAM (GRED + 4 * HD * HD * 4)   // 27648 + 36864 = 64512

__global__ __launch_bounds__(256) void gram_kernel()
{
    extern __shared__ char sm[];
    const int tid  = threadIdx.x;
    const int wid  = tid >> 5;
    const int lane = tid & 31;
    const int bh = blockIdx.x;
    const int sp = blockIdx.y;
    const uint32_t sbase = smem_u32(sm);

    const __half* qbase = g_qT + (size_t)bh * HD * NTOK + sp * TOKSP;
    const __half* kbase = g_kT + (size_t)bh * HD * NTOK + sp * TOKSP;

    // loader: 768 16B-chunks per stage, 3 per thread
    uint32_t ldst[3];
    const __half* lsrc[3];
#pragma unroll
    for (int i = 0; i < 3; i++) {
        int c = tid + i * 256;
        int cc = (c < 384) ? c : c - 384;
        int r = cc >> 3, seg = cc & 7;
        ldst[i] = sbase + ((c < 384) ? 0 : GTILE) + r * GROWB + seg * 16;
        lsrc[i] = ((c < 384) ? qbase : kbase) + (size_t)r * NTOK + seg * 8;
    }
    auto load_stage = [&](int kc, int s) {
#pragma unroll
        for (int i = 0; i < 3; i++)
            CP16(ldst[i] + s * GSTAGE, lsrc[i] + kc);
    };

    const int g  = lane >> 3;
    const int r8 = lane & 7;
    const uint32_t a_off = (uint32_t)(((g & 1) * 8 + r8) * GROWB + (g >> 1) * 16);
    const uint32_t b_off = (uint32_t)((((g >> 1) & 1) * 8 + r8) * GROWB + (g & 1) * 16);

    float acc[3][6][4];
#pragma unroll
    for (int i = 0; i < 3; i++)
#pragma unroll
        for (int j = 0; j < 6; j++)
#pragma unroll
            for (int q = 0; q < 4; q++) acc[i][j][q] = 0.f;

    // norm state (warps 4-7)
    const int t2 = ((wid - 4) & 1) * 32 + lane;   // 0..63 within pair
    const bool isq = (wid == 4 || wid == 5);
    float nsum = 0.f;

    load_stage(0, 0);
    CP_COMMIT();

    for (int c = 0; c < SPLIT; c++) {             // 7 chunks of 64 tokens
        if (c + 1 < SPLIT) {
            load_stage((c + 1) * 64, (c + 1) & 1);
            CP_COMMIT();
            CP_WAIT1();
        } else {
            CP_WAIT0();
        }
        __syncthreads();
        const uint32_t st = sbase + (c & 1) * GSTAGE;
        if (wid < 4) {
            const uint32_t kb = wid * 32;         // this warp's k16 slice
            uint32_t af[3][4], bf[6][2];
#pragma unroll
            for (int mt = 0; mt < 3; mt++)
                ldsm4(af[mt], st + a_off + mt * 16 * GROWB + kb);
#pragma unroll
            for (int j = 0; j < 3; j++) {
                uint32_t t4[4];
                ldsm4(t4, st + GTILE + b_off + j * 16 * GROWB + kb);
                bf[j * 2 + 0][0] = t4[0]; bf[j * 2 + 0][1] = t4[1];
                bf[j * 2 + 1][0] = t4[2]; bf[j * 2 + 1][1] = t4[3];
            }
#pragma unroll
            for (int mt = 0; mt < 3; mt++)
#pragma unroll
                for (int nt = 0; nt < 6; nt++)
                    mma16816(acc[mt][nt], af[mt], bf[nt]);
        } else if (t2 < 48) {
            const uint32_t rowaddr = st + (isq ? 0 : GTILE) + t2 * GROWB;
#pragma unroll
            for (int i = 0; i < 32; i++) {
                uint32_t u;
                asm volatile("ld.shared.b32 %0, [%1];" : "=r"(u) : "r"(rowaddr + i * 4));
                float2 f = __half22float2(*(__half2*)&u);
                nsum = fmaf(f.x, f.x, nsum);
                nsum = fmaf(f.y, f.y, nsum);
            }
        }
        __syncthreads();
    }

    // write norm partials
    if (wid >= 4 && t2 < 48) {
        float* dst = isq ? g_ssq : g_ssk;
        dst[((size_t)bh * SPLIT + sp) * HD + t2] = nsum;
    }

    // reduce 4 warp partials through smem
    float* red = (float*)(sm + GRED);
    if (wid < 4) {
        float* rw = red + wid * (HD * HD);
#pragma unroll
        for (int mt = 0; mt < 3; mt++)
#pragma unroll
            for (int nt = 0; nt < 6; nt++) {
                int row = mt * 16 + (lane >> 2);
                int col = nt * 8 + (lane & 3) * 2;
                *(float2*)(rw + row * HD + col) = *(float2*)&acc[mt][nt][0];
                *(float2*)(rw + (row + 8) * HD + col) = *(float2*)&acc[mt][nt][2];
            }
    }
    __syncthreads();
    float* gout = g_gram + ((size_t)bh * SPLIT + sp) * (HD * HD);
#pragma unroll
    for (int i = 0; i < 9; i++) {
        int el = tid + i * 256;
        gout[el] = red[el] + red[HD * HD + el] + red[2 * HD * HD + el] + red[3 * HD * HD + el];
    }
}

// ---------------------------------------------------------------------------
// Softmax: reduce partials, normalize, softmax -> fp16 attn. grid BH.
// ---------------------------------------------------------------------------
__global__ __launch_bounds__(256) void softmax_kernel(const float* __restrict__ temperature)
{
    __shared__ float attn[48][52];
    __shared__ float invq[48];
    __shared__ float invk[48];

    const int bh = blockIdx.x;
    const int h = bh & 15;
    const int tid = threadIdx.x;
    const int r = tid >> 4;
    const int c = tid & 15;

    if (tid < 48) {
        float s = 0.f;
#pragma unroll
        for (int p = 0; p < SPLIT; p++)
            s += g_ssq[((size_t)bh * SPLIT + p) * HD + tid];
        invq[tid] = 1.f / fmaxf(sqrtf(s), 1e-12f);
    } else if (tid < 96) {
        float s = 0.f;
#pragma unroll
        for (int p = 0; p < SPLIT; p++)
            s += g_ssk[((size_t)bh * SPLIT + p) * HD + tid - 48];
        invk[tid - 48] = 1.f / fmaxf(sqrtf(s), 1e-12f);
    }

    const float* gin = g_gram + (size_t)bh * SPLIT * (HD * HD);
    float sums[3][3];
#pragma unroll
    for (int i = 0; i < 3; i++)
#pragma unroll
        for (int j = 0; j < 3; j++) {
            float s = 0.f;
            int idx = (3 * r + i) * HD + 3 * c + j;
#pragma unroll
            for (int p = 0; p < SPLIT; p++)
                s += gin[p * (HD * HD) + idx];
            sums[i][j] = s;
        }
    __syncthreads();

    const float temp = temperature[h];
#pragma unroll
    for (int i = 0; i < 3; i++)
#pragma unroll
        for (int j = 0; j < 3; j++)
            attn[3 * r + i][3 * c + j] =
                sums[i][j] * invq[3 * r + i] * invk[3 * c + j] * temp;
    __syncthreads();

    const int lane = tid & 31;
    const int w = tid >> 5;
    for (int d = w; d < 48; d += 8) {
        float x1 = attn[d][lane];
        float x2 = (lane < 16) ? attn[d][32 + lane] : -1e30f;
        float m = fmaxf(x1, x2);
#pragma unroll
        for (int o = 16; o > 0; o >>= 1)
            m = fmaxf(m, __shfl_xor_sync(0xffffffffu, m, o));
        float p1 = expf(x1 - m);
        float p2 = (lane < 16) ? expf(x2 - m) : 0.f;
        float s = p1 + p2;
#pragma unroll
        for (int o = 16; o > 0; o >>= 1)
            s += __shfl_xor_sync(0xffffffffu, s, o);
        float inv = 1.f / s;
        __half* arow = g_attnh + (size_t)bh * (HD * HD) + d * HD;
        arow[lane] = __float2half_rn(p1 * inv);
        if (lane < 16) arow[32 + lane] = __float2half_rn(p2 * inv);
    }
}

// ---------------------------------------------------------------------------
// AV via mma: out[token][h*48+d] = sum_e v[token][e] * attn[d][e].
// grid (BH, SPLIT). A = v tiles (128 tokens x 48e), B = attn (48d x 48e, regs).
// ---------------------------------------------------------------------------
#define VROWB  112                 // 48 fp16 = 96B data + 16B pad
#define ATN_B  (48 * VROWB)        // 5376 (attn tile)
#define VSTG   (128 * VROWB)       // 14336
#define SMEM_AV (ATN_B + 2 * VSTG) // 34048

__global__ __launch_bounds__(256) void av_kernel()
{
    extern __shared__ char sm[];
    const int tid  = threadIdx.x;
    const int wid  = tid >> 5;
    const int lane = tid & 31;
    const int bh = blockIdx.x;
    const int sp = blockIdx.y;
    const int b = bh >> 4;
    const int h = bh & 15;
    const uint32_t sbase = smem_u32(sm);
    const uint32_t vs0 = sbase + ATN_B;

    const size_t tokflat = (size_t)b * NTOK + sp * TOKSP;

    // load attn tile 48x48 fp16 into smem (padded rows)
    for (int idx = tid; idx < 288; idx += 256) {
        int row = idx / 6, seg = idx % 6;
        uint4 val = *(const uint4*)(g_attnh + (size_t)bh * (HD * HD) + row * HD + seg * 8);
        *(uint4*)(sm + row * VROWB + seg * 16) = val;
    }

    // v loader: 768 16B-chunks per 128-token stage, 3 per thread
    int lrow[3], lseg[3];
#pragma unroll
    for (int i = 0; i < 3; i++) {
        int cc = tid + i * 256;
        lrow[i] = cc / 6;
        lseg[i] = cc % 6;
    }
    auto load_stage = [&](int t0, int rows, int s) {
#pragma unroll
        for (int i = 0; i < 3; i++) {
            if (lrow[i] < rows) {
                const __half* src = g_v + (tokflat + t0 + lrow[i]) * CH + h * HD + lseg[i] * 8;
                CP16(vs0 + s * VSTG + lrow[i] * VROWB + lseg[i] * 16, src);
            }
        }
    };

    const int g  = lane >> 3;
    const int r8 = lane & 7;
    const uint32_t a_off = (uint32_t)(((g & 1) * 8 + r8) * VROWB + (g >> 1) * 16);
    const uint32_t b_off = (uint32_t)((((g >> 1) & 1) * 8 + r8) * VROWB + (g & 1) * 16);

    load_stage(0, 128, 0);
    CP_COMMIT();
    __syncthreads();   // attn tile ready (regular stores) for all threads

    // preload attn B-frags: 3 k16 x 3 groups -> 18 n8-tile halves
    uint32_t bf[3][6][2];
#pragma unroll
    for (int k16 = 0; k16 < 3; k16++) {
#pragma unroll
        for (int j = 0; j < 3; j++) {
            uint32_t t4[4];
            ldsm4(t4, sbase + b_off + j * 16 * VROWB + k16 * 32);
            bf[k16][j * 2 + 0][0] = t4[0]; bf[k16][j * 2 + 0][1] = t4[1];
            bf[k16][j * 2 + 1][0] = t4[2]; bf[k16][j * 2 + 1][1] = t4[3];
        }
    }

    const int NIT = (TOKSP + 127) / 128;   // 4 (last has 64 rows)
    for (int it = 0; it < NIT; it++) {
        const int rows_this = min(128, TOKSP - it * 128);
        if (it + 1 < NIT) {
            load_stage((it + 1) * 128, min(128, TOKSP - (it + 1) * 128), (it + 1) & 1);
            CP_COMMIT();
            CP_WAIT1();
        } else {
            CP_WAIT0();
        }
        __syncthreads();

        if (wid * 16 < rows_this) {
            const uint32_t st = vs0 + (it & 1) * VSTG + wid * 16 * VROWB;
            float acc[6][4];
#pragma unroll
            for (int j = 0; j < 6; j++)
#pragma unroll
                for (int q = 0; q < 4; q++) acc[j][q] = 0.f;
#pragma unroll
            for (int k16 = 0; k16 < 3; k16++) {
                uint32_t af[4];
                ldsm4(af, st + a_off + k16 * 32);
#pragma unroll
                for (int j = 0; j < 6; j++)
                    mma16816(acc[j], af, bf[k16][j]);
            }
            // store fp16 to g_ah
            const size_t trow = tokflat + it * 128 + wid * 16 + (lane >> 2);
#pragma unroll
            for (int j = 0; j < 6; j++) {
                int d = j * 8 + (lane & 3) * 2;
                __half2 h0 = __floats2half2_rn(acc[j][0], acc[j][1]);
                __half2 h1 = __floats2half2_rn(acc[j][2], acc[j][3]);
                *(__half2*)(g_ah + trow * CH + h * HD + d) = h0;
                *(__half2*)(g_ah + (trow + 8) * CH + h * HD + d) = h1;
            }
        }
        __syncthreads();
    }
}

// ---------------------------------------------------------------------------
// Launch sequence
// ---------------------------------------------------------------------------
extern "C" void kernel_launch(void* const* d_in, const int* in_sizes, int n_in,
                              void* d_out, int out_size)
{
    const float* x           = (const float*)d_in[0];
    const float* qkv_w       = (const float*)d_in[1];
    const float* temperature = (const float*)d_in[2];
    const float* proj_w      = (const float*)d_in[3];
    const float* proj_b      = (const float*)d_in[4];
    float* out = (float*)d_out;

    __half *xh, *ah, *wq, *wp, *qT, *kT, *vv;
    cudaGetSymbolAddress((void**)&xh, g_xh);
    cudaGetSymbolAddress((void**)&ah, g_ah);
    cudaGetSymbolAddress((void**)&wq, g_wq);
    cudaGetSymbolAddress((void**)&wp, g_wp);
    cudaGetSymbolAddress((void**)&qT, g_qT);
    cudaGetSymbolAddress((void**)&kT, g_kT);
    cudaGetSymbolAddress((void**)&vv, g_v);

    cudaFuncSetAttribute(gemm_qkv, cudaFuncAttributeMaxDynamicSharedMemorySize, SMEM_GEMM);
    cudaFuncSetAttribute(gemm_mma, cudaFuncAttributeMaxDynamicSharedMemorySize, SMEM_GEMM);
    cudaFuncSetAttribute(gram_kernel, cudaFuncAttributeMaxDynamicSharedMemorySize, SMEM_GRAM);
    cudaFuncSetAttribute(av_kernel, cudaFuncAttributeMaxDynamicSharedMemorySize, SMEM_AV);

    int n4 = MROWS * KDIM / 4;
    conv_kernel<<<(n4 + 255) / 256, 256>>>((const float4*)x, (__half2*)xh, n4);

    tconv_kernel<<<dim3((3 * CH) / 32, KDIM / 32), dim3(32, 8)>>>(
        qkv_w, wq, KDIM, 3 * CH);
    tconv_kernel<<<dim3(CH / 32, KDIM / 32), dim3(32, 8)>>>(
        proj_w, wp, KDIM, CH);

    gemm_qkv<<<dim3((3 * CH) / 128, MROWS / 128), 256, SMEM_GEMM>>>(
        xh, wq, qT, kT, vv);

    gram_kernel<<<dim3(BH, SPLIT), 256, SMEM_GRAM>>>();
    softmax_kernel<<<BH, 256>>>(temperature);
    av_kernel<<<dim3(BH, SPLIT), 256, SMEM_AV>>>();

    gemm_mma<<<dim3(CH / 128, MROWS / 128), 256, SMEM_GEMM>>>(
        ah, wp, out, CH, proj_b);
}

// round 9
// speedup vs baseline: 3.4491x; 1.0598x over previous
#include <cuda_runtime.h>
#include <cuda_fp16.h>
#include <math.h>
#include <stdint.h>
#include <stddef.h>

#define BATCH 16
#define NTOK  3136
#define CH    768
#define NH    16
#define HD    48
#define KDIM  768
#define MROWS (BATCH*NTOK)   // 50176
#define BH    (BATCH*NH)     // 256
#define SPLIT 7
#define TOKSP (NTOK/SPLIT)   // 448

// ----------------------------- device scratch ------------------------------
__device__ __half g_xh  [(size_t)MROWS * KDIM];
__device__ __half g_qT  [(size_t)BH * HD * NTOK];   // [bh][d][n] fp16
__device__ __half g_kT  [(size_t)BH * HD * NTOK];
__device__ __half g_v   [(size_t)MROWS * CH];       // [token][h*48+d] fp16
__device__ __half g_ah  [(size_t)MROWS * CH];
__device__ __half g_wq  [(size_t)(3 * CH) * KDIM];
__device__ __half g_wp  [(size_t)CH * KDIM];
__device__ float  g_gram[(size_t)BH * SPLIT * HD * HD];
__device__ float  g_ssq [(size_t)BH * SPLIT * HD];
__device__ float  g_ssk [(size_t)BH * SPLIT * HD];
__device__ __half g_attnh[(size_t)BH * HD * HD];

// ----------------------------- PTX helpers ---------------------------------
__device__ __forceinline__ uint32_t smem_u32(const void* p) {
    return (uint32_t)__cvta_generic_to_shared(p);
}

__device__ __forceinline__ void mma16816(float* c, const uint32_t* a, const uint32_t* b) {
    asm volatile(
        "mma.sync.aligned.m16n8k16.row.col.f32.f16.f16.f32 "
        "{%0,%1,%2,%3}, {%4,%5,%6,%7}, {%8,%9}, {%0,%1,%2,%3};"
        : "+f"(c[0]), "+f"(c[1]), "+f"(c[2]), "+f"(c[3])
        : "r"(a[0]), "r"(a[1]), "r"(a[2]), "r"(a[3]), "r"(b[0]), "r"(b[1]));
}

__device__ __forceinline__ void ldsm4(uint32_t* r, uint32_t addr) {
    asm volatile("ldmatrix.sync.aligned.m8n8.x4.shared.b16 {%0,%1,%2,%3}, [%4];"
        : "=r"(r[0]), "=r"(r[1]), "=r"(r[2]), "=r"(r[3]) : "r"(addr));
}

#define CP16(dst, src) \
    asm volatile("cp.async.cg.shared.global [%0], [%1], 16;" :: "r"(dst), "l"(src))
#define CP_COMMIT()  asm volatile("cp.async.commit_group;" ::: "memory")
#define CP_WAIT0()   asm volatile("cp.async.wait_group 0;" ::: "memory")
#define CP_WAIT1()   asm volatile("cp.async.wait_group 1;" ::: "memory")

// ---------------------------------------------------------------------------
// fp32 -> fp16 convert
// ---------------------------------------------------------------------------
__global__ void conv_kernel(const float4* __restrict__ in,
                            __half2* __restrict__ out, int n4)
{
    int i = blockIdx.x * blockDim.x + threadIdx.x;
    if (i >= n4) return;
    float4 v = in[i];
    out[2 * i + 0] = __floats2half2_rn(v.x, v.y);
    out[2 * i + 1] = __floats2half2_rn(v.z, v.w);
}

// ---------------------------------------------------------------------------
// Transpose + convert: W[K,N] fp32 -> Wt [N,K] fp16
// ---------------------------------------------------------------------------
__global__ void tconv_kernel(const float* __restrict__ W,
                             __half* __restrict__ T, int K, int N)
{
    __shared__ float tile[32][33];
    int n0 = blockIdx.x * 32, k0 = blockIdx.y * 32;
    int tx = threadIdx.x, ty = threadIdx.y;   // 32 x 8
#pragma unroll
    for (int j = 0; j < 32; j += 8)
        tile[ty + j][tx] = W[(size_t)(k0 + ty + j) * N + n0 + tx];
    __syncthreads();
#pragma unroll
    for (int j = 0; j < 32; j += 8)
        T[(size_t)(n0 + ty + j) * K + k0 + tx] = __float2half_rn(tile[tx][ty + j]);
}

// ---------------------------------------------------------------------------
// GEMM geometry: K-chunk 64, 3 stages, one barrier per iteration.
// Rows 64 fp16 = 128B data + 16B pad = 144B (stride 9 x 16B: conflict-free).
// ---------------------------------------------------------------------------
#define ROWB     144
#define TILE_B   (128 * ROWB)                // 18432
#define STAGE_B  (2 * TILE_B)                // 36864
#define NSTAGE   3
#define SMEM_GEMM (NSTAGE * STAGE_B)         // 110592
#define KC       64
#define NITER    (KDIM / KC)                 // 12

// Shared mainloop body (loader + pipeline + MMA), parameterized by epilogue.
#define GEMM_PRELUDE(Aptr, Bptr)                                               \
    extern __shared__ char sm[];                                               \
    const int tid  = threadIdx.x;                                              \
    const int wid  = tid >> 5;                                                 \
    const int lane = tid & 31;                                                 \
    const size_t m0 = (size_t)blockIdx.y * 128;                                \
    const size_t n0 = (size_t)blockIdx.x * 128;                                \
    const int ltile = tid >> 7;                                                \
    const int lsub  = tid & 127;                                               \
    const int lrow0 = lsub >> 3;          /* 0..15, + i*16 */                  \
    const int lseg  = lsub & 7;                                                \
    const __half* lsrc = (ltile == 0) ? (Aptr) + m0 * KDIM : (Bptr) + n0 * KDIM; \
    const uint32_t sbase = smem_u32(sm);                                       \
    const uint32_t ldst0 = sbase + ltile * TILE_B + lrow0 * ROWB + lseg * 16;  \
    const __half* lsrc0 = lsrc + (size_t)lrow0 * KDIM + lseg * 8;              \
    auto load_stage = [&](int kc, int s) {                                     \
        uint32_t d = ldst0 + s * STAGE_B;                                      \
        const __half* g = lsrc0 + kc;                                          \
        _Pragma("unroll")                                                      \
        for (int i = 0; i < 8; i++)                                            \
            CP16(d + i * 16 * ROWB, g + (size_t)i * 16 * KDIM);                \
    };                                                                         \
    const int warp_m = wid & 1;                                                \
    const int warp_n = wid >> 1;                                               \
    const int gq  = lane >> 3;                                                 \
    const int r8 = lane & 7;                                                   \
    const uint32_t a_off = (uint32_t)((warp_m * 64 + (gq & 1) * 8 + r8) * ROWB + (gq >> 1) * 16); \
    const uint32_t b_off = (uint32_t)((warp_n * 32 + ((gq >> 1) & 1) * 8 + r8) * ROWB + (gq & 1) * 16); \
    float acc[4][4][4];                                                        \
    _Pragma("unroll")                                                          \
    for (int i = 0; i < 4; i++)                                                \
        _Pragma("unroll")                                                      \
        for (int j = 0; j < 4; j++)                                            \
            _Pragma("unroll")                                                  \
            for (int q = 0; q < 4; q++) acc[i][j][q] = 0.f;                    \
    load_stage(0, 0);  CP_COMMIT();                                            \
    load_stage(KC, 1); CP_COMMIT();                                            \
    for (int it = 0; it < NITER; it++) {                                       \
        CP_WAIT1();                                                            \
        __syncthreads();                                                       \
        if (it + 2 < NITER) load_stage((it + 2) * KC, (it + 2) % NSTAGE);      \
        CP_COMMIT();                                                           \
        const uint32_t st = sbase + (it % NSTAGE) * STAGE_B;                   \
        uint32_t af[2][4][4];                                                  \
        _Pragma("unroll")                                                      \
        for (int mt = 0; mt < 4; mt++)                                         \
            ldsm4(af[0][mt], st + a_off + mt * 16 * ROWB);                     \
        _Pragma("unroll")                                                      \
        for (int kk = 0; kk < 4; kk++) {                                       \
            const uint32_t kb = kk * 32;                                       \
            const int cur = kk & 1;                                            \
            uint32_t bf[4][2], t4[4];                                          \
            ldsm4(t4, st + TILE_B + b_off + kb);                               \
            bf[0][0] = t4[0]; bf[0][1] = t4[1];                                \
            bf[1][0] = t4[2]; bf[1][1] = t4[3];                                \
            ldsm4(t4, st + TILE_B + b_off + 16 * ROWB + kb);                   \
            bf[2][0] = t4[0]; bf[2][1] = t4[1];                                \
            bf[3][0] = t4[2]; bf[3][1] = t4[3];                                \
            if (kk < 3) {                                                      \
                _Pragma("unroll")                                              \
                for (int mt = 0; mt < 4; mt++)                                 \
                    ldsm4(af[cur ^ 1][mt], st + a_off + mt * 16 * ROWB + kb + 32); \
            }                                                                  \
            _Pragma("unroll")                                                  \
            for (int mt = 0; mt < 4; mt++)                                     \
                _Pragma("unroll")                                              \
                for (int nt = 0; nt < 4; nt++)                                 \
                    mma16816(acc[mt][nt], af[cur][mt], bf[nt]);                \
        }                                                                      \
    }

// ---------------------------------------------------------------------------
// GEMM1: qkv = x @ qkv_w^T, fp16 outputs in XCA layouts.
// ---------------------------------------------------------------------------
__global__ __launch_bounds__(256, 2) void gemm_qkv(
    const __half* __restrict__ A, const __half* __restrict__ B,
    __half* __restrict__ Qt, __half* __restrict__ Kt, __half* __restrict__ Vp)
{
    GEMM_PRELUDE(A, B)

    // ---- epilogue ----
    CP_WAIT0();
    __syncthreads();   // all smem reads done; safe to reuse sm
    const int section = (int)(n0 / 768);   // 0:q 1:k 2:v
    const int crow = warp_m * 64 + (lane >> 2);
    const int ccol = warp_n * 32 + (lane & 3) * 2;

    if (section == 2) {
#pragma unroll
        for (int mt = 0; mt < 4; mt++) {
#pragma unroll
            for (int nt = 0; nt < 4; nt++) {
                size_t row = m0 + crow + mt * 16;
                int vc = (int)(n0 - 1536) + ccol + nt * 8;
                __half2 h0 = __floats2half2_rn(acc[mt][nt][0], acc[mt][nt][1]);
                __half2 h1 = __floats2half2_rn(acc[mt][nt][2], acc[mt][nt][3]);
                *(__half2*)(Vp + row * CH + vc) = h0;
                *(__half2*)(Vp + (row + 8) * CH + vc) = h1;
            }
        }
    } else {
        // transpose through smem: [col 128][token 128], row stride 272B
#pragma unroll
        for (int mt = 0; mt < 4; mt++) {
#pragma unroll
            for (int nt = 0; nt < 4; nt++) {
                int col = ccol + nt * 8;
                int row = crow + mt * 16;
                *(__half*)(sm + (size_t)col * 272 + row * 2)             = __float2half_rn(acc[mt][nt][0]);
                *(__half*)(sm + (size_t)(col + 1) * 272 + row * 2)       = __float2half_rn(acc[mt][nt][1]);
                *(__half*)(sm + (size_t)col * 272 + (row + 8) * 2)       = __float2half_rn(acc[mt][nt][2]);
                *(__half*)(sm + (size_t)(col + 1) * 272 + (row + 8) * 2) = __float2half_rn(acc[mt][nt][3]);
            }
        }
        __syncthreads();
        __half* dst = (section == 0) ? Qt : Kt;
        const int base_gc = (int)n0 - section * 768;
#pragma unroll
        for (int i = 0; i < 8; i++) {
            int idx = tid + i * 256;          // 0..2047
            int col = idx >> 4, tv = idx & 15;
            uint4 val = *(uint4*)(sm + (size_t)col * 272 + tv * 16);
            int gc = base_gc + col;
            int hh = gc / 48, dd = gc - hh * 48;
            size_t tok = m0 + tv * 8;
            int b = (int)(tok / NTOK);
            int n = (int)(tok - (size_t)b * NTOK);
            *(uint4*)(dst + ((size_t)(b * 16 + hh) * HD + dd) * NTOK + n) = val;
        }
    }
}

// ---------------------------------------------------------------------------
// GEMM2: out = att @ proj_w^T + bias, fp32 out.
// ---------------------------------------------------------------------------
__global__ __launch_bounds__(256, 2) void gemm_mma(
    const __half* __restrict__ A, const __half* __restrict__ B,
    float* __restrict__ C, int N, const float* __restrict__ bias)
{
    GEMM_PRELUDE(A, B)

    const int crow = warp_m * 64 + (lane >> 2);
    const int ccol = warp_n * 32 + (lane & 3) * 2;
#pragma unroll
    for (int mt = 0; mt < 4; mt++) {
#pragma unroll
        for (int nt = 0; nt < 4; nt++) {
            float b0 = __ldg(bias + n0 + ccol + nt * 8);
            float b1 = __ldg(bias + n0 + ccol + nt * 8 + 1);
            float2 v0 = {acc[mt][nt][0] + b0, acc[mt][nt][1] + b1};
            float2 v1 = {acc[mt][nt][2] + b0, acc[mt][nt][3] + b1};
            float* p0 = C + (m0 + crow + mt * 16) * (size_t)N + n0 + ccol + nt * 8;
            float* p1 = p0 + 8 * (size_t)N;
            *(float2*)p0 = v0;
            *(float2*)p1 = v1;
        }
    }
}

// ---------------------------------------------------------------------------
// Gram via mma (unchanged from R8).
// ---------------------------------------------------------------------------
#define GROWB  144
#define GTILE  (48 * GROWB)
#define GSTAGE (2 * GTILE)
#define GRED   (2 * GSTAGE)
#define SMEM_GRAM (GRED + 4 * HD * HD * 4)

__global__ __launch_bounds__(256) void gram_kernel()
{
    extern __shared__ char sm[];
    const int tid  = threadIdx.x;
    const int wid  = tid >> 5;
    const int lane = tid & 31;
    const int bh = blockIdx.x;
    const int sp = blockIdx.y;
    const uint32_t sbase = smem_u32(sm);

    const __half* qbase = g_qT + (size_t)bh * HD * NTOK + sp * TOKSP;
    const __half* kbase = g_kT + (size_t)bh * HD * NTOK + sp * TOKSP;

    uint32_t ldst[3];
    const __half* lsrc[3];
#pragma unroll
    for (int i = 0; i < 3; i++) {
        int c = tid + i * 256;
        int cc = (c < 384) ? c : c - 384;
        int r = cc >> 3, seg = cc & 7;
        ldst[i] = sbase + ((c < 384) ? 0 : GTILE) + r * GROWB + seg * 16;
        lsrc[i] = ((c < 384) ? qbase : kbase) + (size_t)r * NTOK + seg * 8;
    }
    auto load_stage = [&](int kc, int s) {
#pragma unroll
        for (int i = 0; i < 3; i++)
            CP16(ldst[i] + s * GSTAGE, lsrc[i] + kc);
    };

    const int g  = lane >> 3;
    const int r8 = lane & 7;
    const uint32_t a_off = (uint32_t)(((g & 1) * 8 + r8) * GROWB + (g >> 1) * 16);
    const uint32_t b_off = (uint32_t)((((g >> 1) & 1) * 8 + r8) * GROWB + (g & 1) * 16);

    float acc[3][6][4];
#pragma unroll
    for (int i = 0; i < 3; i++)
#pragma unroll
        for (int j = 0; j < 6; j++)
#pragma unroll
            for (int q = 0; q < 4; q++) acc[i][j][q] = 0.f;

    const int t2 = ((wid - 4) & 1) * 32 + lane;
    const bool isq = (wid == 4 || wid == 5);
    float nsum = 0.f;

    load_stage(0, 0);
    CP_COMMIT();

    for (int c = 0; c < SPLIT; c++) {
        if (c + 1 < SPLIT) {
            load_stage((c + 1) * 64, (c + 1) & 1);
            CP_COMMIT();
            CP_WAIT1();
        } else {
            CP_WAIT0();
        }
        __syncthreads();
        const uint32_t st = sbase + (c & 1) * GSTAGE;
        if (wid < 4) {
            const uint32_t kb = wid * 32;
            uint32_t af[3][4], bf[6][2];
#pragma unroll
            for (int mt = 0; mt < 3; mt++)
                ldsm4(af[mt], st + a_off + mt * 16 * GROWB + kb);
#pragma unroll
            for (int j = 0; j < 3; j++) {
                uint32_t t4[4];
                ldsm4(t4, st + GTILE + b_off + j * 16 * GROWB + kb);
                bf[j * 2 + 0][0] = t4[0]; bf[j * 2 + 0][1] = t4[1];
                bf[j * 2 + 1][0] = t4[2]; bf[j * 2 + 1][1] = t4[3];
            }
#pragma unroll
            for (int mt = 0; mt < 3; mt++)
#pragma unroll
                for (int nt = 0; nt < 6; nt++)
                    mma16816(acc[mt][nt], af[mt], bf[nt]);
        } else if (t2 < 48) {
            const uint32_t rowaddr = st + (isq ? 0 : GTILE) + t2 * GROWB;
#pragma unroll
            for (int i = 0; i < 32; i++) {
                uint32_t u;
                asm volatile("ld.shared.b32 %0, [%1];" : "=r"(u) : "r"(rowaddr + i * 4));
                float2 f = __half22float2(*(__half2*)&u);
                nsum = fmaf(f.x, f.x, nsum);
                nsum = fmaf(f.y, f.y, nsum);
            }
        }
        __syncthreads();
    }

    if (wid >= 4 && t2 < 48) {
        float* dst = isq ? g_ssq : g_ssk;
        dst[((size_t)bh * SPLIT + sp) * HD + t2] = nsum;
    }

    float* red = (float*)(sm + GRED);
    if (wid < 4) {
        float* rw = red + wid * (HD * HD);
#pragma unroll
        for (int mt = 0; mt < 3; mt++)
#pragma unroll
            for (int nt = 0; nt < 6; nt++) {
                int row = mt * 16 + (lane >> 2);
                int col = nt * 8 + (lane & 3) * 2;
                *(float2*)(rw + row * HD + col) = *(float2*)&acc[mt][nt][0];
                *(float2*)(rw + (row + 8) * HD + col) = *(float2*)&acc[mt][nt][2];
            }
    }
    __syncthreads();
    float* gout = g_gram + ((size_t)bh * SPLIT + sp) * (HD * HD);
#pragma unroll
    for (int i = 0; i < 9; i++) {
        int el = tid + i * 256;
        gout[el] = red[el] + red[HD * HD + el] + red[2 * HD * HD + el] + red[3 * HD * HD + el];
    }
}

// ---------------------------------------------------------------------------
// Softmax (unchanged from R8).
// ---------------------------------------------------------------------------
__global__ __launch_bounds__(256) void softmax_kernel(const float* __restrict__ temperature)
{
    __shared__ float attn[48][52];
    __shared__ float invq[48];
    __shared__ float invk[48];

    const int bh = blockIdx.x;
    const int h = bh & 15;
    const int tid = threadIdx.x;
    const int r = tid >> 4;
    const int c = tid & 15;

    if (tid < 48) {
        float s = 0.f;
#pragma unroll
        for (int p = 0; p < SPLIT; p++)
            s += g_ssq[((size_t)bh * SPLIT + p) * HD + tid];
        invq[tid] = 1.f / fmaxf(sqrtf(s), 1e-12f);
    } else if (tid < 96) {
        float s = 0.f;
#pragma unroll
        for (int p = 0; p < SPLIT; p++)
            s += g_ssk[((size_t)bh * SPLIT + p) * HD + tid - 48];
        invk[tid - 48] = 1.f / fmaxf(sqrtf(s), 1e-12f);
    }

    const float* gin = g_gram + (size_t)bh * SPLIT * (HD * HD);
    float sums[3][3];
#pragma unroll
    for (int i = 0; i < 3; i++)
#pragma unroll
        for (int j = 0; j < 3; j++) {
            float s = 0.f;
            int idx = (3 * r + i) * HD + 3 * c + j;
#pragma unroll
            for (int p = 0; p < SPLIT; p++)
                s += gin[p * (HD * HD) + idx];
            sums[i][j] = s;
        }
    __syncthreads();

    const float temp = temperature[h];
#pragma unroll
    for (int i = 0; i < 3; i++)
#pragma unroll
        for (int j = 0; j < 3; j++)
            attn[3 * r + i][3 * c + j] =
                sums[i][j] * invq[3 * r + i] * invk[3 * c + j] * temp;
    __syncthreads();

    const int lane = tid & 31;
    const int w = tid >> 5;
    for (int d = w; d < 48; d += 8) {
        float x1 = attn[d][lane];
        float x2 = (lane < 16) ? attn[d][32 + lane] : -1e30f;
        float m = fmaxf(x1, x2);
#pragma unroll
        for (int o = 16; o > 0; o >>= 1)
            m = fmaxf(m, __shfl_xor_sync(0xffffffffu, m, o));
        float p1 = expf(x1 - m);
        float p2 = (lane < 16) ? expf(x2 - m) : 0.f;
        float s = p1 + p2;
#pragma unroll
        for (int o = 16; o > 0; o >>= 1)
            s += __shfl_xor_sync(0xffffffffu, s, o);
        float inv = 1.f / s;
        __half* arow = g_attnh + (size_t)bh * (HD * HD) + d * HD;
        arow[lane] = __float2half_rn(p1 * inv);
        if (lane < 16) arow[32 + lane] = __float2half_rn(p2 * inv);
    }
}

// ---------------------------------------------------------------------------
// AV via mma (unchanged from R8).
// ---------------------------------------------------------------------------
#define VROWB  112
#define ATN_B  (48 * VROWB)
#define VSTG   (128 * VROWB)
#define SMEM_AV (ATN_B + 2 * VSTG)

__global__ __launch_bounds__(256) void av_kernel()
{
    extern __shared__ char sm[];
    const int tid  = threadIdx.x;
    const int wid  = tid >> 5;
    const int lane = tid & 31;
    const int bh = blockIdx.x;
    const int sp = blockIdx.y;
    const int b = bh >> 4;
    const int h = bh & 15;
    const uint32_t sbase = smem_u32(sm);
    const uint32_t vs0 = sbase + ATN_B;

    const size_t tokflat = (size_t)b * NTOK + sp * TOKSP;

    for (int idx = tid; idx < 288; idx += 256) {
        int row = idx / 6, seg = idx % 6;
        uint4 val = *(const uint4*)(g_attnh + (size_t)bh * (HD * HD) + row * HD + seg * 8);
        *(uint4*)(sm + row * VROWB + seg * 16) = val;
    }

    int lrow[3], lseg[3];
#pragma unroll
    for (int i = 0; i < 3; i++) {
        int cc = tid + i * 256;
        lrow[i] = cc / 6;
        lseg[i] = cc % 6;
    }
    auto load_stage = [&](int t0, int rows, int s) {
#pragma unroll
        for (int i = 0; i < 3; i++) {
            if (lrow[i] < rows) {
                const __half* src = g_v + (tokflat + t0 + lrow[i]) * CH + h * HD + lseg[i] * 8;
                CP16(vs0 + s * VSTG + lrow[i] * VROWB + lseg[i] * 16, src);
            }
        }
    };

    const int g  = lane >> 3;
    const int r8 = lane & 7;
    const uint32_t a_off = (uint32_t)(((g & 1) * 8 + r8) * VROWB + (g >> 1) * 16);
    const uint32_t b_off = (uint32_t)((((g >> 1) & 1) * 8 + r8) * VROWB + (g & 1) * 16);

    load_stage(0, 128, 0);
    CP_COMMIT();
    __syncthreads();

    uint32_t bf[3][6][2];
#pragma unroll
    for (int k16 = 0; k16 < 3; k16++) {
#pragma unroll
        for (int j = 0; j < 3; j++) {
            uint32_t t4[4];
            ldsm4(t4, sbase + b_off + j * 16 * VROWB + k16 * 32);
            bf[k16][j * 2 + 0][0] = t4[0]; bf[k16][j * 2 + 0][1] = t4[1];
            bf[k16][j * 2 + 1][0] = t4[2]; bf[k16][j * 2 + 1][1] = t4[3];
        }
    }

    const int NIT = (TOKSP + 127) / 128;
    for (int it = 0; it < NIT; it++) {
        const int rows_this = min(128, TOKSP - it * 128);
        if (it + 1 < NIT) {
            load_stage((it + 1) * 128, min(128, TOKSP - (it + 1) * 128), (it + 1) & 1);
            CP_COMMIT();
            CP_WAIT1();
        } else {
            CP_WAIT0();
        }
        __syncthreads();

        if (wid * 16 < rows_this) {
            const uint32_t st = vs0 + (it & 1) * VSTG + wid * 16 * VROWB;
            float acc[6][4];
#pragma unroll
            for (int j = 0; j < 6; j++)
#pragma unroll
                for (int q = 0; q < 4; q++) acc[j][q] = 0.f;
#pragma unroll
            for (int k16 = 0; k16 < 3; k16++) {
                uint32_t af[4];
                ldsm4(af, st + a_off + k16 * 32);
#pragma unroll
                for (int j = 0; j < 6; j++)
                    mma16816(acc[j], af, bf[k16][j]);
            }
            const size_t trow = tokflat + it * 128 + wid * 16 + (lane >> 2);
#pragma unroll
            for (int j = 0; j < 6; j++) {
                int d = j * 8 + (lane & 3) * 2;
                __half2 h0 = __floats2half2_rn(acc[j][0], acc[j][1]);
                __half2 h1 = __floats2half2_rn(acc[j][2], acc[j][3]);
                *(__half2*)(g_ah + trow * CH + h * HD + d) = h0;
                *(__half2*)(g_ah + (trow + 8) * CH + h * HD + d) = h1;
            }
        }
        __syncthreads();
    }
}

// ---------------------------------------------------------------------------
// Launch sequence
// ---------------------------------------------------------------------------
extern "C" void kernel_launch(void* const* d_in, const int* in_sizes, int n_in,
                              void* d_out, int out_size)
{
    const float* x           = (const float*)d_in[0];
    const float* qkv_w       = (const float*)d_in[1];
    const float* temperature = (const float*)d_in[2];
    const float* proj_w      = (const float*)d_in[3];
    const float* proj_b      = (const float*)d_in[4];
    float* out = (float*)d_out;

    __half *xh, *ah, *wq, *wp, *qT, *kT, *vv;
    cudaGetSymbolAddress((void**)&xh, g_xh);
    cudaGetSymbolAddress((void**)&ah, g_ah);
    cudaGetSymbolAddress((void**)&wq, g_wq);
    cudaGetSymbolAddress((void**)&wp, g_wp);
    cudaGetSymbolAddress((void**)&qT, g_qT);
    cudaGetSymbolAddress((void**)&kT, g_kT);
    cudaGetSymbolAddress((void**)&vv, g_v);

    cudaFuncSetAttribute(gemm_qkv, cudaFuncAttributeMaxDynamicSharedMemorySize, SMEM_GEMM);
    cudaFuncSetAttribute(gemm_mma, cudaFuncAttributeMaxDynamicSharedMemorySize, SMEM_GEMM);
    cudaFuncSetAttribute(gram_kernel, cudaFuncAttributeMaxDynamicSharedMemorySize, SMEM_GRAM);
    cudaFuncSetAttribute(av_kernel, cudaFuncAttributeMaxDynamicSharedMemorySize, SMEM_AV);

    int n4 = MROWS * KDIM / 4;
    conv_kernel<<<(n4 + 255) / 256, 256>>>((const float4*)x, (__half2*)xh, n4);

    tconv_kernel<<<dim3((3 * CH) / 32, KDIM / 32), dim3(32, 8)>>>(
        qkv_w, wq, KDIM, 3 * CH);
    tconv_kernel<<<dim3(CH / 32, KDIM / 32), dim3(32, 8)>>>(
        proj_w, wp, KDIM, CH);

    gemm_qkv<<<dim3((3 * CH) / 128, MROWS / 128), 256, SMEM_GEMM>>>(
        xh, wq, qT, kT, vv);

    gram_kernel<<<dim3(BH, SPLIT), 256, SMEM_GRAM>>>();
    softmax_kernel<<<BH, 256>>>(temperature);
    av_kernel<<<dim3(BH, SPLIT), 256, SMEM_AV>>>();

    gemm_mma<<<dim3(CH / 128, MROWS / 128), 256, SMEM_GEMM>>>(
        ah, wp, out, CH, proj_b);
}